// round 9
// baseline (speedup 1.0000x reference)
#include <cuda_runtime.h>
#include <cuda_bf16.h>
#include <math.h>
#include <stdint.h>

#define BB 2
#define SS 2048
#define HH 16
#define DD 64
#define HID 1024
#define NTOK (BB * SS)
#define LOG2E 1.4426950408889634f
#define QSCALE (0.125f * LOG2E)
#define MASKADD (-10000.0f * LOG2E)

// -------- scratch (allocation-free __device__ globals) --------
__device__ __nv_bfloat16 g_xh[(size_t)NTOK * HID];
__device__ __nv_bfloat16 g_xl[(size_t)NTOK * HID];
__device__ __nv_bfloat16 g_Wth[(size_t)3 * HID * HID];   // W^T [n][k] hi
__device__ __nv_bfloat16 g_Wtl[(size_t)3 * HID * HID];   // W^T [n][k] lo
__device__ __nv_bfloat16 g_Qh[(size_t)NTOK * HID];       // [b][h][s][d]
__device__ __nv_bfloat16 g_Ql[(size_t)NTOK * HID];
__device__ __nv_bfloat16 g_Kh[(size_t)NTOK * HID];
__device__ __nv_bfloat16 g_Vh[(size_t)NTOK * HID];
__device__ __nv_bfloat16 g_Vl[(size_t)NTOK * HID];

// ===================== helpers =====================
__device__ __forceinline__ uint32_t smem_u32(const void* p) {
    uint32_t a;
    asm("{ .reg .u64 t; cvta.to.shared.u64 t, %1; cvt.u32.u64 %0, t; }" : "=r"(a) : "l"(p));
    return a;
}
__device__ __forceinline__ uint32_t sw128(uint32_t o) { return o ^ ((o >> 3) & 0x70); }

__device__ __forceinline__ void ldsm4(uint32_t r[4], uint32_t addr) {
    asm volatile("ldmatrix.sync.aligned.m8n8.x4.shared.b16 {%0,%1,%2,%3}, [%4];"
                 : "=r"(r[0]), "=r"(r[1]), "=r"(r[2]), "=r"(r[3]) : "r"(addr));
}
__device__ __forceinline__ void ldsm4t(uint32_t r[4], uint32_t addr) {
    asm volatile("ldmatrix.sync.aligned.m8n8.x4.trans.shared.b16 {%0,%1,%2,%3}, [%4];"
                 : "=r"(r[0]), "=r"(r[1]), "=r"(r[2]), "=r"(r[3]) : "r"(addr));
}
__device__ __forceinline__ void mma16816(float c[4], const uint32_t a[4],
                                         uint32_t b0, uint32_t b1) {
    asm volatile(
        "mma.sync.aligned.m16n8k16.row.col.f32.bf16.bf16.f32 "
        "{%0,%1,%2,%3}, {%4,%5,%6,%7}, {%8,%9}, {%0,%1,%2,%3};"
        : "+f"(c[0]), "+f"(c[1]), "+f"(c[2]), "+f"(c[3])
        : "r"(a[0]), "r"(a[1]), "r"(a[2]), "r"(a[3]), "r"(b0), "r"(b1));
}
__device__ __forceinline__ uint32_t prmt_hi(float a, float b) {
    uint32_t d;
    asm("prmt.b32 %0, %1, %2, 0x7632;" : "=r"(d)
        : "r"(__float_as_uint(a)), "r"(__float_as_uint(b)));
    return d;
}
__device__ __forceinline__ float hi_trunc(float v) {
    return __uint_as_float(__float_as_uint(v) & 0xFFFF0000u);
}
__device__ __forceinline__ uint32_t packlo(float e0, float e1) {
    uint32_t d;
    asm("cvt.rn.bf16x2.f32 %0, %1, %2;" : "=r"(d) : "f"(e1), "f"(e0));
    return d;
}
// FFMA-only exp2
__device__ __forceinline__ float exp2p(float x) {
    x = fmaxf(x, -100.0f);
    float t = x + 12582912.0f;
    int   k = __float_as_int(t) - 0x4B400000;
    float f = x - (t - 12582912.0f);
    float r = 1.3333558146428443e-3f;
    r = fmaf(r, f, 9.618129107628477e-3f);
    r = fmaf(r, f, 5.550410866482158e-2f);
    r = fmaf(r, f, 2.402265069591007e-1f);
    r = fmaf(r, f, 6.931471805599453e-1f);
    r = fmaf(r, f, 1.0f);
    return r * __int_as_float(0x3F800000 + (k << 23));
}
__device__ __forceinline__ void cpa16(uint32_t s, const void* g) {
    asm volatile("cp.async.cg.shared.global [%0], [%1], 16;" :: "r"(s), "l"(g));
}
__device__ __forceinline__ void cpa4(uint32_t s, const void* g) {
    asm volatile("cp.async.ca.shared.global [%0], [%1], 4;" :: "r"(s), "l"(g));
}
#define CPA_COMMIT() asm volatile("cp.async.commit_group;")
#define CPA_WAIT2()  asm volatile("cp.async.wait_group 2;")
#define CPA_WAIT1()  asm volatile("cp.async.wait_group 1;")
#define CPA_WAIT0()  asm volatile("cp.async.wait_group 0;")

// ===================== prep kernels (RN hi, residual lo) =====================
__global__ void split_x(const float* __restrict__ x) {
    int i = blockIdx.x * 256 + threadIdx.x;
    float v = x[i];
    __nv_bfloat16 h = __float2bfloat16(v);
    g_xh[i] = h;
    g_xl[i] = __float2bfloat16(v - __bfloat162float(h));
}

__global__ void split_w(const float* __restrict__ Wq, const float* __restrict__ Wk,
                        const float* __restrict__ Wv) {
    __shared__ float t[32][33];
    int z = blockIdx.z;
    const float* W = (z == 0) ? Wq : (z == 1) ? Wk : Wv;
    int tx = threadIdx.x, ty = threadIdx.y;
    t[ty][tx] = W[(size_t)(blockIdx.y * 32 + ty) * HID + blockIdx.x * 32 + tx];
    __syncthreads();
    int n = blockIdx.x * 32 + ty;
    int k = blockIdx.y * 32 + tx;
    float v = t[tx][ty];
    __nv_bfloat16 h = __float2bfloat16(v);
    size_t o = (size_t)z * HID * HID + (size_t)n * HID + k;
    g_Wth[o] = h;
    g_Wtl[o] = __float2bfloat16(v - __bfloat162float(h));
}

// ===================== QKV GEMM: BM128 x BN128 x BK32, 512 thr, 3-stage =============
// Padded 80B rows (conflict-free, no swizzle). Stage = Ah(10240) Al Bh Bl = 40960.
#define GROW 80
#define GTILE (128 * GROW)          // 10240
#define GSTG  (4 * GTILE)           // 40960
#define GSMEM (3 * GSTG)            // 122880
#define GNCH  32                    // K chunks of 32

__global__ __launch_bounds__(512, 1)
void qkv_gemm_mma(const float* __restrict__ bq, const float* __restrict__ bk,
                  const float* __restrict__ bv) {
    extern __shared__ __align__(1024) char sm[];
    const int tid = threadIdx.x, lane = tid & 31, wid = tid >> 5;
    const int wm = wid & 3, wn = wid >> 2;          // 4 x 4 warp grid, 32x32 tiles
    const int z = blockIdx.z;
    const int m0 = blockIdx.y * 128;
    const int n0 = blockIdx.x * 128;

    const __nv_bfloat16* Wh = g_Wth + (size_t)z * HID * HID;
    const __nv_bfloat16* Wl = g_Wtl + (size_t)z * HID * HID;
    const float* bias = (z == 0) ? bq : (z == 1) ? bk : bv;
    const uint32_t smb = smem_u32(sm);

    // loader: 512 threads, 1 x 16B per tile each. row = tid>>2, ch = tid&3.
    const int lrow = tid >> 2, lch = tid & 3;
    const uint32_t lso = (uint32_t)(lrow * GROW + lch * 16);
    auto issue = [&](int c, int s) {
        const uint32_t sb = smb + s * GSTG;
        const int k0 = c * 32;
        size_t ga = (size_t)(m0 + lrow) * HID + k0 + lch * 8;
        size_t gb = (size_t)(n0 + lrow) * HID + k0 + lch * 8;
        cpa16(sb + lso,             g_xh + ga);
        cpa16(sb + GTILE + lso,     g_xl + ga);
        cpa16(sb + 2 * GTILE + lso, Wh + gb);
        cpa16(sb + 3 * GTILE + lso, Wl + gb);
        CPA_COMMIT();
    };

    float acc[2][4][4];
#pragma unroll
    for (int i = 0; i < 2; i++)
#pragma unroll
        for (int j = 0; j < 4; j++)
#pragma unroll
            for (int v = 0; v < 4; v++) acc[i][j][v] = 0.f;

    issue(0, 0); issue(1, 1); issue(2, 2);

    const uint32_t rAo = (uint32_t)((wm * 32 + (lane & 15)) * GROW) + ((lane >> 4) ? 16u : 0u);
    const uint32_t rBo = (uint32_t)((wn * 32 + (lane & 15)) * GROW) + ((lane >> 4) ? 16u : 0u);

    for (int c = 0; c < GNCH; c++) {
        const int s = c % 3;
        const uint32_t sb = smb + s * GSTG;
        if (c <= GNCH - 3) CPA_WAIT2();
        else if (c == GNCH - 2) CPA_WAIT1();
        else CPA_WAIT0();
        __syncthreads();

#pragma unroll
        for (int kk = 0; kk < 2; kk++) {
            const uint32_t aA = sb + rAo + kk * 32;
            const uint32_t aB = sb + 2 * GTILE + rBo + kk * 32;
            uint32_t ah[2][4], al[2][4], bh[2][4], bl[2][4];
            ldsm4(ah[0], aA);                 ldsm4(ah[1], aA + 16 * GROW);
            ldsm4(al[0], aA + GTILE);         ldsm4(al[1], aA + GTILE + 16 * GROW);
            ldsm4(bh[0], aB);                 ldsm4(bh[1], aB + 16 * GROW);
            ldsm4(bl[0], aB + GTILE);         ldsm4(bl[1], aB + GTILE + 16 * GROW);
#pragma unroll
            for (int g = 0; g < 2; g++) {
#pragma unroll
                for (int mi = 0; mi < 2; mi++) {
                    mma16816(acc[mi][2 * g],     ah[mi], bh[g][0], bh[g][2]);
                    mma16816(acc[mi][2 * g + 1], ah[mi], bh[g][1], bh[g][3]);
                    mma16816(acc[mi][2 * g],     ah[mi], bl[g][0], bl[g][2]);
                    mma16816(acc[mi][2 * g + 1], ah[mi], bl[g][1], bl[g][3]);
                    mma16816(acc[mi][2 * g],     al[mi], bh[g][0], bh[g][2]);
                    mma16816(acc[mi][2 * g + 1], al[mi], bh[g][1], bh[g][3]);
                }
            }
        }
        __syncthreads();
        if (c + 3 < GNCH) issue(c + 3, (c + 3) % 3);
    }

    // epilogue: bias (+Q scale), RN hi + residual lo, store [b,h,s,d]
    __nv_bfloat16* outh = (z == 0) ? g_Qh : (z == 1) ? g_Kh : g_Vh;
    __nv_bfloat16* outl = (z == 0) ? g_Ql : g_Vl;   // z==1 lo never consumed
    const float sc = (z == 0) ? QSCALE : 1.0f;
#pragma unroll
    for (int mi = 0; mi < 2; mi++) {
        int r0 = m0 + wm * 32 + mi * 16 + (lane >> 2);
#pragma unroll
        for (int nj = 0; nj < 4; nj++) {
            int col = n0 + wn * 32 + nj * 8 + 2 * (lane & 3);
            float b0v = __ldg(&bias[col]), b1v = __ldg(&bias[col + 1]);
#pragma unroll
            for (int half = 0; half < 2; half++) {
                int r = r0 + half * 8;
                float v0 = (acc[mi][nj][half * 2 + 0] + b0v) * sc;
                float v1 = (acc[mi][nj][half * 2 + 1] + b1v) * sc;
                size_t off = (((size_t)((r >> 11) * HH + (col >> 6)) * SS +
                               (r & (SS - 1))) * DD) + (col & (DD - 1));
                uint32_t hp = packlo(v0, v1);
                *(uint32_t*)(outh + off) = hp;
                if (z != 1) {
                    float hf0 = __uint_as_float(hp << 16);
                    float hf1 = __uint_as_float(hp & 0xFFFF0000u);
                    *(uint32_t*)(outl + off) = packlo(v0 - hf0, v1 - hf1);
                }
            }
        }
    }
}

// ===================== flash attention (R7: 3-stage cp.async, 3-term PV) ===========
// CTA: 128 q rows, 8 warps. 64 keys/chunk, 32 chunks.
// stage s@s*24576: Kh@0(8K) Vh@8192 Vl@16384. mask ints @73728+s*256.
#define ASTAGE 24576
#define AADDER (3 * ASTAGE)          // 73728
#define ASMEM  (AADDER + 3 * 256)    // 74496
#define ACH 32

__global__ __launch_bounds__(256, 2)
void attn_mma(const int* __restrict__ mask, float* __restrict__ out) {
    extern __shared__ __align__(1024) char sm[];
    const int tid = threadIdx.x, lane = tid & 31, wid = tid >> 5;
    const int q0 = blockIdx.x * 128;
    const int h = blockIdx.y, b = blockIdx.z;
    const size_t hb = (size_t)(b * HH + h) * SS * DD;
    const uint32_t smb = smem_u32(sm);

    // ---- prologue: stage Q hi/lo, read A-frags ----
#pragma unroll
    for (int j = 0; j < 4; j++) {
        int idx = tid + 256 * j;
        int row = idx >> 3, ch = idx & 7;
        uint32_t so = sw128((uint32_t)(row * 128 + ch * 16));
        size_t g = hb + (size_t)(q0 + row) * DD + ch * 8;
        *(uint4*)(sm + so)         = *(const uint4*)(g_Qh + g);
        *(uint4*)(sm + 16384 + so) = *(const uint4*)(g_Ql + g);
    }
    __syncthreads();
    uint32_t qh[4][4], ql[4][4];
    {
        int r = wid * 16 + (lane & 15);
#pragma unroll
        for (int kk = 0; kk < 4; kk++) {
            int cB = kk * 32 + (lane >> 4) * 16;
            uint32_t qa = smb + sw128((uint32_t)(r * 128 + cB));
            ldsm4(qh[kk], qa);
            ldsm4(ql[kk], qa + 16384);
        }
    }
    __syncthreads();

    auto issue = [&](int c, int s) {
        const uint32_t sb = smb + s * ASTAGE;
        const int c0 = c * 64;
#pragma unroll
        for (int j = 0; j < 2; j++) {
            int idx = tid + 256 * j;
            int row = idx >> 3, ch = idx & 7;
            uint32_t so = sw128((uint32_t)(row * 128 + ch * 16));
            size_t g = hb + (size_t)(c0 + row) * DD + ch * 8;
            cpa16(sb + so,         g_Kh + g);
            cpa16(sb + 8192 + so,  g_Vh + g);
            cpa16(sb + 16384 + so, g_Vl + g);
        }
        if (tid < 64) cpa4(smb + AADDER + s * 256 + tid * 4, mask + b * SS + c0 + tid);
        CPA_COMMIT();
    };

    float ctx[8][4];
#pragma unroll
    for (int i = 0; i < 8; i++)
#pragma unroll
        for (int j = 0; j < 4; j++) ctx[i][j] = 0.f;
    float l0s = 0.f, l1s = 0.f;

    issue(0, 0); issue(1, 1); issue(2, 2);

    const int rk = lane & 15;
    const int kcol = 2 * (lane & 3);

    for (int c = 0; c < ACH; c++) {
        const int s = c % 3;
        const uint32_t sb = smb + s * ASTAGE;
        if (c <= ACH - 3) CPA_WAIT2();
        else if (c == ACH - 2) CPA_WAIT1();
        else CPA_WAIT0();
        __syncthreads();

        // ---- S = Q K^T (2-term: qh*kh + ql*kh) ----
        float sacc[8][4];
#pragma unroll
        for (int i = 0; i < 8; i++)
#pragma unroll
            for (int j = 0; j < 4; j++) sacc[i][j] = 0.f;

#pragma unroll
        for (int kk = 0; kk < 4; kk++) {
            const int cB = kk * 32 + (lane >> 4) * 16;
            const uint32_t ka = sb + sw128((uint32_t)(rk * 128 + cB));
#pragma unroll
            for (int g = 0; g < 4; g++) {
                uint32_t kh[4];
                ldsm4(kh, ka + g * 2048);
                mma16816(sacc[2 * g],     qh[kk], kh[0], kh[2]);
                mma16816(sacc[2 * g + 1], qh[kk], kh[1], kh[3]);
                mma16816(sacc[2 * g],     ql[kk], kh[0], kh[2]);
                mma16816(sacc[2 * g + 1], ql[kk], kh[1], kh[3]);
            }
        }

        // ---- softmax numerator, fixed base (scores provably small) ----
        const int* madd = (const int*)(sm + AADDER + s * 256);
#pragma unroll
        for (int nj = 0; nj < 8; nj++) {
            float a0 = madd[nj * 8 + kcol]     ? 0.f : MASKADD;
            float a1 = madd[nj * 8 + kcol + 1] ? 0.f : MASKADD;
            float p0 = exp2p(sacc[nj][0] + a0);
            float p1 = exp2p(sacc[nj][1] + a1);
            float p2 = exp2p(sacc[nj][2] + a0);
            float p3 = exp2p(sacc[nj][3] + a1);
            l0s += p0 + p1; l1s += p2 + p3;
            sacc[nj][0] = p0; sacc[nj][1] = p1;
            sacc[nj][2] = p2; sacc[nj][3] = p3;
        }

        // ---- pack P (trunc hi + residual lo) ----
        uint32_t ph[4][4], pl[4][4];
#pragma unroll
        for (int kg = 0; kg < 4; kg++) {
            const float* s0 = sacc[2 * kg];
            const float* s1 = sacc[2 * kg + 1];
            ph[kg][0] = prmt_hi(s0[0], s0[1]);
            ph[kg][1] = prmt_hi(s0[2], s0[3]);
            ph[kg][2] = prmt_hi(s1[0], s1[1]);
            ph[kg][3] = prmt_hi(s1[2], s1[3]);
            pl[kg][0] = packlo(s0[0] - hi_trunc(s0[0]), s0[1] - hi_trunc(s0[1]));
            pl[kg][1] = packlo(s0[2] - hi_trunc(s0[2]), s0[3] - hi_trunc(s0[3]));
            pl[kg][2] = packlo(s1[0] - hi_trunc(s1[0]), s1[1] - hi_trunc(s1[1]));
            pl[kg][3] = packlo(s1[2] - hi_trunc(s1[2]), s1[3] - hi_trunc(s1[3]));
        }

        // ---- ctx += P V (3-term) ----
#pragma unroll
        for (int dg = 0; dg < 4; dg++) {
            const int cB = dg * 32 + (lane >> 4) * 16;
            const uint32_t va = sb + 8192 + sw128((uint32_t)((lane & 15) * 128 + cB));
#pragma unroll
            for (int kg = 0; kg < 4; kg++) {
                uint32_t vh[4], vl[4];
                ldsm4t(vh, va + kg * 2048);
                ldsm4t(vl, va + 8192 + kg * 2048);
                mma16816(ctx[2 * dg],     ph[kg], vh[0], vh[1]);
                mma16816(ctx[2 * dg + 1], ph[kg], vh[2], vh[3]);
                mma16816(ctx[2 * dg],     ph[kg], vl[0], vl[1]);
                mma16816(ctx[2 * dg + 1], ph[kg], vl[2], vl[3]);
                mma16816(ctx[2 * dg],     pl[kg], vh[0], vh[1]);
                mma16816(ctx[2 * dg + 1], pl[kg], vh[2], vh[3]);
            }
        }
        __syncthreads();
        if (c + 3 < ACH) issue(c + 3, (c + 3) % 3);
    }

    // ---- l reduction across the quad, then write out ----
    l0s += __shfl_xor_sync(0xFFFFFFFFu, l0s, 1);
    l0s += __shfl_xor_sync(0xFFFFFFFFu, l0s, 2);
    l1s += __shfl_xor_sync(0xFFFFFFFFu, l1s, 1);
    l1s += __shfl_xor_sync(0xFFFFFFFFu, l1s, 2);
    const float inv0 = 1.0f / l0s, inv1 = 1.0f / l1s;
    const int r0 = q0 + wid * 16 + (lane >> 2);
    const int dbase = 2 * (lane & 3);
#pragma unroll
    for (int nj = 0; nj < 8; nj++) {
        int d = nj * 8 + dbase;
        float2 v0 = make_float2(ctx[nj][0] * inv0, ctx[nj][1] * inv0);
        float2 v1 = make_float2(ctx[nj][2] * inv1, ctx[nj][3] * inv1);
        *(float2*)&out[(size_t)(b * SS + r0) * HID + h * DD + d] = v0;
        *(float2*)&out[(size_t)(b * SS + r0 + 8) * HID + h * DD + d] = v1;
    }
}

// ===================== launch =====================
extern "C" void kernel_launch(void* const* d_in, const int* in_sizes, int n_in,
                              void* d_out, int out_size) {
    const float* x    = (const float*)d_in[0];
    const int*   mask = (const int*)d_in[1];
    const float* Wq   = (const float*)d_in[2];
    const float* bq   = (const float*)d_in[3];
    const float* Wk   = (const float*)d_in[4];
    const float* bk   = (const float*)d_in[5];
    const float* Wv   = (const float*)d_in[6];
    const float* bv   = (const float*)d_in[7];
    float* out = (float*)d_out;

    static int attr_done = 0;
    if (!attr_done) {
        cudaFuncSetAttribute(qkv_gemm_mma,
                             cudaFuncAttributeMaxDynamicSharedMemorySize, GSMEM);
        cudaFuncSetAttribute(attn_mma,
                             cudaFuncAttributeMaxDynamicSharedMemorySize, ASMEM);
        attr_done = 1;
    }

    split_x<<<(NTOK * HID) / 256, 256>>>(x);
    dim3 wgrid(HID / 32, HID / 32, 3);
    split_w<<<wgrid, dim3(32, 32)>>>(Wq, Wk, Wv);

    dim3 ggrid(HID / 128, NTOK / 128, 3);
    qkv_gemm_mma<<<ggrid, 512, GSMEM>>>(bq, bk, bv);

    dim3 agrid(SS / 128, HH, BB);
    attn_mma<<<agrid, 256, ASMEM>>>(mask, out);
}

// round 10
// speedup vs baseline: 1.7236x; 1.7236x over previous
#include <cuda_runtime.h>
#include <cuda_fp16.h>
#include <math.h>
#include <stdint.h>

#define BB 2
#define SS 2048
#define HH 16
#define DD 64
#define HID 1024
#define NTOK (BB * SS)
#define LOG2E 1.4426950408889634f
#define QSCALE (0.125f * LOG2E)
#define MASKADD (-10000.0f * LOG2E)

// -------- scratch (allocation-free __device__ globals) --------
__device__ __half g_x[(size_t)NTOK * HID];               // x, fp16
__device__ __half g_Wth[(size_t)3 * HID * HID];          // W^T [n][k] hi
__device__ __half g_Wtl[(size_t)3 * HID * HID];          // W^T [n][k] lo (residual)
__device__ __half g_Qh[(size_t)NTOK * HID];              // [b][h][s][d]
__device__ __half g_Kh[(size_t)NTOK * HID];
__device__ __half g_Vh[(size_t)NTOK * HID];
__device__ __half g_Vl[(size_t)NTOK * HID];

// ===================== helpers =====================
__device__ __forceinline__ uint32_t smem_u32(const void* p) {
    uint32_t a;
    asm("{ .reg .u64 t; cvta.to.shared.u64 t, %1; cvt.u32.u64 %0, t; }" : "=r"(a) : "l"(p));
    return a;
}
__device__ __forceinline__ uint32_t sw128(uint32_t o) { return o ^ ((o >> 3) & 0x70); }

__device__ __forceinline__ void ldsm4(uint32_t r[4], uint32_t addr) {
    asm volatile("ldmatrix.sync.aligned.m8n8.x4.shared.b16 {%0,%1,%2,%3}, [%4];"
                 : "=r"(r[0]), "=r"(r[1]), "=r"(r[2]), "=r"(r[3]) : "r"(addr));
}
__device__ __forceinline__ void ldsm4t(uint32_t r[4], uint32_t addr) {
    asm volatile("ldmatrix.sync.aligned.m8n8.x4.trans.shared.b16 {%0,%1,%2,%3}, [%4];"
                 : "=r"(r[0]), "=r"(r[1]), "=r"(r[2]), "=r"(r[3]) : "r"(addr));
}
// fp16 MMA, f32 accumulate
__device__ __forceinline__ void mma16816(float c[4], const uint32_t a[4],
                                         uint32_t b0, uint32_t b1) {
    asm volatile(
        "mma.sync.aligned.m16n8k16.row.col.f32.f16.f16.f32 "
        "{%0,%1,%2,%3}, {%4,%5,%6,%7}, {%8,%9}, {%0,%1,%2,%3};"
        : "+f"(c[0]), "+f"(c[1]), "+f"(c[2]), "+f"(c[3])
        : "r"(a[0]), "r"(a[1]), "r"(a[2]), "r"(a[3]), "r"(b0), "r"(b1));
}
// pack RN-fp16 pair: e0 -> low half, e1 -> high half
__device__ __forceinline__ uint32_t packh(float e0, float e1) {
    __half2 h = __floats2half2_rn(e0, e1);
    return *reinterpret_cast<uint32_t*>(&h);
}
// FFMA-only exp2
__device__ __forceinline__ float exp2p(float x) {
    x = fmaxf(x, -100.0f);
    float t = x + 12582912.0f;
    int   k = __float_as_int(t) - 0x4B400000;
    float f = x - (t - 12582912.0f);
    float r = 1.3333558146428443e-3f;
    r = fmaf(r, f, 9.618129107628477e-3f);
    r = fmaf(r, f, 5.550410866482158e-2f);
    r = fmaf(r, f, 2.402265069591007e-1f);
    r = fmaf(r, f, 6.931471805599453e-1f);
    r = fmaf(r, f, 1.0f);
    return r * __int_as_float(0x3F800000 + (k << 23));
}
__device__ __forceinline__ void cpa16(uint32_t s, const void* g) {
    asm volatile("cp.async.cg.shared.global [%0], [%1], 16;" :: "r"(s), "l"(g));
}
__device__ __forceinline__ void cpa4(uint32_t s, const void* g) {
    asm volatile("cp.async.ca.shared.global [%0], [%1], 4;" :: "r"(s), "l"(g));
}
#define CPA_COMMIT() asm volatile("cp.async.commit_group;")
#define CPA_WAIT2()  asm volatile("cp.async.wait_group 2;")
#define CPA_WAIT1()  asm volatile("cp.async.wait_group 1;")
#define CPA_WAIT0()  asm volatile("cp.async.wait_group 0;")

// ===================== prep kernels =====================
__global__ void conv_x(const float* __restrict__ x) {
    int i = blockIdx.x * 256 + threadIdx.x;
    g_x[i] = __float2half_rn(x[i]);
}

__global__ void conv_w(const float* __restrict__ Wq, const float* __restrict__ Wk,
                       const float* __restrict__ Wv) {
    __shared__ float t[32][33];
    int z = blockIdx.z;
    const float* W = (z == 0) ? Wq : (z == 1) ? Wk : Wv;
    int tx = threadIdx.x, ty = threadIdx.y;
    t[ty][tx] = W[(size_t)(blockIdx.y * 32 + ty) * HID + blockIdx.x * 32 + tx];
    __syncthreads();
    int n = blockIdx.x * 32 + ty;
    int k = blockIdx.y * 32 + tx;
    float v = t[tx][ty];
    __half h = __float2half_rn(v);
    size_t o = (size_t)z * HID * HID + (size_t)n * HID + k;
    g_Wth[o] = h;
    g_Wtl[o] = __float2half_rn(v - __half2float(h));
}

// ===================== QKV GEMM (fp16 2-term: x*Wh + x*Wl) =====================
// BM=128, BN=64, BK=64. stage: A@0(16K) Bh@16K(8K) Bl@24K(8K) = 32K; 3 stages.
#define GSTAGE 32768
#define GSMEM  (3 * GSTAGE)      // 98304
#define NCHUNK 16

__global__ __launch_bounds__(256, 2)
void qkv_gemm_mma(const float* __restrict__ bq, const float* __restrict__ bk,
                  const float* __restrict__ bv) {
    extern __shared__ __align__(1024) char sm[];
    const int tid = threadIdx.x, lane = tid & 31, wid = tid >> 5;
    const int wm = wid & 3, wn = wid >> 2;
    const int z = blockIdx.z;
    const int m0 = blockIdx.y * 128;
    const int n0 = blockIdx.x * 64;

    const __half* Wh = g_Wth + (size_t)z * HID * HID;
    const __half* Wl = g_Wtl + (size_t)z * HID * HID;
    const float* bias = (z == 0) ? bq : (z == 1) ? bk : bv;
    const uint32_t smb = smem_u32(sm);

    auto issue = [&](int c, int s) {
        const uint32_t sb = smb + s * GSTAGE;
        const int k0 = c * 64;
#pragma unroll
        for (int j = 0; j < 4; j++) {               // A: 128 rows x 8 x 16B
            int idx = tid + 256 * j;
            int row = idx >> 3, ch = idx & 7;
            uint32_t so = sw128((uint32_t)(row * 128 + ch * 16));
            cpa16(sb + so, g_x + (size_t)(m0 + row) * HID + k0 + ch * 8);
        }
#pragma unroll
        for (int j = 0; j < 2; j++) {               // B: 64 rows x 8 x 16B, hi+lo
            int idx = tid + 256 * j;
            int row = idx >> 3, ch = idx & 7;
            uint32_t so = sw128((uint32_t)(row * 128 + ch * 16));
            size_t gb = (size_t)(n0 + row) * HID + k0 + ch * 8;
            cpa16(sb + 16384 + so, Wh + gb);
            cpa16(sb + 24576 + so, Wl + gb);
        }
        CPA_COMMIT();
    };

    float acc[2][4][4];
#pragma unroll
    for (int i = 0; i < 2; i++)
#pragma unroll
        for (int j = 0; j < 4; j++)
#pragma unroll
            for (int v = 0; v < 4; v++) acc[i][j][v] = 0.f;

    issue(0, 0); issue(1, 1); issue(2, 2);

    // precomputed swizzled offsets (stage-invariant)
    uint32_t offA[4], offB[4];
    {
        const int rA = wm * 32 + (lane & 15);
        const int rB = wn * 32 + (lane & 15);
#pragma unroll
        for (int kk = 0; kk < 4; kk++) {
            const int cB = kk * 32 + (lane >> 4) * 16;
            offA[kk] = sw128((uint32_t)(rA * 128 + cB));
            offB[kk] = 16384 + sw128((uint32_t)(rB * 128 + cB));
        }
    }

    for (int c = 0; c < NCHUNK; c++) {
        const int s = c % 3;
        const uint32_t sb = smb + s * GSTAGE;
        if (c <= NCHUNK - 3) CPA_WAIT2();
        else if (c == NCHUNK - 2) CPA_WAIT1();
        else CPA_WAIT0();
        __syncthreads();

#pragma unroll
        for (int kk = 0; kk < 4; kk++) {
            const uint32_t aA = sb + offA[kk];
            const uint32_t aB = sb + offB[kk];
            uint32_t ah[2][4], bh[2][4], bl[2][4];
            ldsm4(ah[0], aA);            ldsm4(ah[1], aA + 2048);
            ldsm4(bh[0], aB);            ldsm4(bh[1], aB + 2048);
            ldsm4(bl[0], aB + 8192);     ldsm4(bl[1], aB + 10240);
#pragma unroll
            for (int g = 0; g < 2; g++) {
#pragma unroll
                for (int mi = 0; mi < 2; mi++) {
                    mma16816(acc[mi][2 * g],     ah[mi], bh[g][0], bh[g][2]);
                    mma16816(acc[mi][2 * g + 1], ah[mi], bh[g][1], bh[g][3]);
                    mma16816(acc[mi][2 * g],     ah[mi], bl[g][0], bl[g][2]);
                    mma16816(acc[mi][2 * g + 1], ah[mi], bl[g][1], bl[g][3]);
                }
            }
        }
        __syncthreads();
        if (c + 3 < NCHUNK) issue(c + 3, (c + 3) % 3);
    }

    // epilogue: bias (+Q scale), store fp16 [b,h,s,d]; V also residual-lo
    __half* outh = (z == 0) ? g_Qh : (z == 1) ? g_Kh : g_Vh;
    const float sc = (z == 0) ? QSCALE : 1.0f;
#pragma unroll
    for (int mi = 0; mi < 2; mi++) {
        int r0 = m0 + wm * 32 + mi * 16 + (lane >> 2);
#pragma unroll
        for (int nj = 0; nj < 4; nj++) {
            int col = n0 + wn * 32 + nj * 8 + 2 * (lane & 3);
            float b0v = __ldg(&bias[col]), b1v = __ldg(&bias[col + 1]);
#pragma unroll
            for (int half_ = 0; half_ < 2; half_++) {
                int r = r0 + half_ * 8;
                float v0 = (acc[mi][nj][half_ * 2 + 0] + b0v) * sc;
                float v1 = (acc[mi][nj][half_ * 2 + 1] + b1v) * sc;
                size_t off = (((size_t)((r >> 11) * HH + (col >> 6)) * SS +
                               (r & (SS - 1))) * DD) + (col & (DD - 1));
                uint32_t hp = packh(v0, v1);
                *(uint32_t*)(outh + off) = hp;
                if (z == 2) {
                    __half2 hh = *reinterpret_cast<__half2*>(&hp);
                    *(uint32_t*)(g_Vl + off) =
                        packh(v0 - __half2float(hh.x), v1 - __half2float(hh.y));
                }
            }
        }
    }
}

// ===================== flash attention (fp16: 1-term QK, 2-term PV) ================
// CTA: 128 q rows, 8 warps. 64 keys/chunk, 32 chunks.
// stage s@s*24576: Kh@0(8K) Vh@8192 Vl@16384. mask ints @73728+s*256.
#define ASTAGE 24576
#define AADDER (3 * ASTAGE)          // 73728
#define ASMEM  (AADDER + 3 * 256)    // 74496
#define ACH 32

__global__ __launch_bounds__(256, 2)
void attn_mma(const int* __restrict__ mask, float* __restrict__ out) {
    extern __shared__ __align__(1024) char sm[];
    const int tid = threadIdx.x, lane = tid & 31, wid = tid >> 5;
    const int q0 = blockIdx.x * 128;
    const int h = blockIdx.y, b = blockIdx.z;
    const size_t hb = (size_t)(b * HH + h) * SS * DD;
    const uint32_t smb = smem_u32(sm);

    // ---- prologue: stage Q, read A-frags ----
#pragma unroll
    for (int j = 0; j < 4; j++) {
        int idx = tid + 256 * j;
        int row = idx >> 3, ch = idx & 7;
        uint32_t so = sw128((uint32_t)(row * 128 + ch * 16));
        *(uint4*)(sm + so) = *(const uint4*)(g_Qh + hb + (size_t)(q0 + row) * DD + ch * 8);
    }
    __syncthreads();
    uint32_t qh[4][4];
    {
        int r = wid * 16 + (lane & 15);
#pragma unroll
        for (int kk = 0; kk < 4; kk++) {
            int cB = kk * 32 + (lane >> 4) * 16;
            ldsm4(qh[kk], smb + sw128((uint32_t)(r * 128 + cB)));
        }
    }
    __syncthreads();

    auto issue = [&](int c, int s) {
        const uint32_t sb = smb + s * ASTAGE;
        const int c0 = c * 64;
#pragma unroll
        for (int j = 0; j < 2; j++) {
            int idx = tid + 256 * j;
            int row = idx >> 3, ch = idx & 7;
            uint32_t so = sw128((uint32_t)(row * 128 + ch * 16));
            size_t g = hb + (size_t)(c0 + row) * DD + ch * 8;
            cpa16(sb + so,         g_Kh + g);
            cpa16(sb + 8192 + so,  g_Vh + g);
            cpa16(sb + 16384 + so, g_Vl + g);
        }
        if (tid < 64) cpa4(smb + AADDER + s * 256 + tid * 4, mask + b * SS + c0 + tid);
        CPA_COMMIT();
    };

    float ctx[8][4];
#pragma unroll
    for (int i = 0; i < 8; i++)
#pragma unroll
        for (int j = 0; j < 4; j++) ctx[i][j] = 0.f;
    float l0s = 0.f, l1s = 0.f;

    issue(0, 0); issue(1, 1); issue(2, 2);

    // precomputed swizzled offsets (stage-invariant)
    uint32_t offK[4], offV[4];
    {
        const int rk = lane & 15;
#pragma unroll
        for (int i = 0; i < 4; i++) {
            const int cB = i * 32 + (lane >> 4) * 16;
            offK[i] = sw128((uint32_t)(rk * 128 + cB));
            offV[i] = 8192 + sw128((uint32_t)(rk * 128 + cB));
        }
    }
    const int kcol = 2 * (lane & 3);

    for (int c = 0; c < ACH; c++) {
        const int s = c % 3;
        const uint32_t sb = smb + s * ASTAGE;
        if (c <= ACH - 3) CPA_WAIT2();
        else if (c == ACH - 2) CPA_WAIT1();
        else CPA_WAIT0();
        __syncthreads();

        // ---- S = Q K^T (1-term fp16) ----
        float sacc[8][4];
#pragma unroll
        for (int i = 0; i < 8; i++)
#pragma unroll
            for (int j = 0; j < 4; j++) sacc[i][j] = 0.f;

#pragma unroll
        for (int kk = 0; kk < 4; kk++) {
            const uint32_t ka = sb + offK[kk];
#pragma unroll
            for (int g = 0; g < 4; g++) {
                uint32_t kh[4];
                ldsm4(kh, ka + g * 2048);
                mma16816(sacc[2 * g],     qh[kk], kh[0], kh[2]);
                mma16816(sacc[2 * g + 1], qh[kk], kh[1], kh[3]);
            }
        }

        // ---- softmax numerator (fixed base), pack P as RN fp16 ----
        const int* madd = (const int*)(sm + AADDER + s * 256);
        uint32_t ph[4][4];
#pragma unroll
        for (int kg = 0; kg < 4; kg++) {
            const float* s0 = sacc[2 * kg];
            const float* s1 = sacc[2 * kg + 1];
            float a0 = madd[kg * 16 + kcol]         ? 0.f : MASKADD;
            float a1 = madd[kg * 16 + kcol + 1]     ? 0.f : MASKADD;
            float a2 = madd[kg * 16 + 8 + kcol]     ? 0.f : MASKADD;
            float a3 = madd[kg * 16 + 8 + kcol + 1] ? 0.f : MASKADD;
            float p00 = exp2p(s0[0] + a0), p01 = exp2p(s0[1] + a1);
            float p02 = exp2p(s0[2] + a0), p03 = exp2p(s0[3] + a1);
            float p10 = exp2p(s1[0] + a2), p11 = exp2p(s1[1] + a3);
            float p12 = exp2p(s1[2] + a2), p13 = exp2p(s1[3] + a3);
            l0s += (p00 + p01) + (p10 + p11);
            l1s += (p02 + p03) + (p12 + p13);
            ph[kg][0] = packh(p00, p01);
            ph[kg][1] = packh(p02, p03);
            ph[kg][2] = packh(p10, p11);
            ph[kg][3] = packh(p12, p13);
        }

        // ---- ctx += P V (2-term: ph*vh + ph*vl) ----
#pragma unroll
        for (int dg = 0; dg < 4; dg++) {
            const uint32_t va = sb + offV[dg];
#pragma unroll
            for (int kg = 0; kg < 4; kg++) {
                uint32_t vh[4], vl[4];
                ldsm4t(vh, va + kg * 2048);
                ldsm4t(vl, va + 8192 + kg * 2048);
                mma16816(ctx[2 * dg],     ph[kg], vh[0], vh[1]);
                mma16816(ctx[2 * dg + 1], ph[kg], vh[2], vh[3]);
                mma16816(ctx[2 * dg],     ph[kg], vl[0], vl[1]);
                mma16816(ctx[2 * dg + 1], ph[kg], vl[2], vl[3]);
            }
        }
        __syncthreads();
        if (c + 3 < ACH) issue(c + 3, (c + 3) % 3);
    }

    // ---- l reduction across the quad, write out [b, s, h*64 + d] ----
    l0s += __shfl_xor_sync(0xFFFFFFFFu, l0s, 1);
    l0s += __shfl_xor_sync(0xFFFFFFFFu, l0s, 2);
    l1s += __shfl_xor_sync(0xFFFFFFFFu, l1s, 1);
    l1s += __shfl_xor_sync(0xFFFFFFFFu, l1s, 2);
    const float inv0 = 1.0f / l0s, inv1 = 1.0f / l1s;
    const int r0 = q0 + wid * 16 + (lane >> 2);
    const int dbase = 2 * (lane & 3);
#pragma unroll
    for (int nj = 0; nj < 8; nj++) {
        int d = nj * 8 + dbase;
        float2 v0 = make_float2(ctx[nj][0] * inv0, ctx[nj][1] * inv0);
        float2 v1 = make_float2(ctx[nj][2] * inv1, ctx[nj][3] * inv1);
        *(float2*)&out[(size_t)(b * SS + r0) * HID + h * DD + d] = v0;
        *(float2*)&out[(size_t)(b * SS + r0 + 8) * HID + h * DD + d] = v1;
    }
}

// ===================== launch =====================
extern "C" void kernel_launch(void* const* d_in, const int* in_sizes, int n_in,
                              void* d_out, int out_size) {
    const float* x    = (const float*)d_in[0];
    const int*   mask = (const int*)d_in[1];
    const float* Wq   = (const float*)d_in[2];
    const float* bq   = (const float*)d_in[3];
    const float* Wk   = (const float*)d_in[4];
    const float* bk   = (const float*)d_in[5];
    const float* Wv   = (const float*)d_in[6];
    const float* bv   = (const float*)d_in[7];
    float* out = (float*)d_out;

    static int attr_done = 0;
    if (!attr_done) {
        cudaFuncSetAttribute(qkv_gemm_mma,
                             cudaFuncAttributeMaxDynamicSharedMemorySize, GSMEM);
        cudaFuncSetAttribute(attn_mma,
                             cudaFuncAttributeMaxDynamicSharedMemorySize, ASMEM);
        attr_done = 1;
    }

    conv_x<<<(NTOK * HID) / 256, 256>>>(x);
    dim3 wgrid(HID / 32, HID / 32, 3);
    conv_w<<<wgrid, dim3(32, 32)>>>(Wq, Wk, Wv);

    dim3 ggrid(HID / 64, NTOK / 128, 3);
    qkv_gemm_mma<<<ggrid, 256, GSMEM>>>(bq, bk, bv);

    dim3 agrid(SS / 128, HH, BB);
    attn_mma<<<agrid, 256, ASMEM>>>(mask, out);
}

// round 11
// speedup vs baseline: 1.9196x; 1.1137x over previous
#include <cuda_runtime.h>
#include <cuda_fp16.h>
#include <math.h>
#include <stdint.h>

#define BB 2
#define SS 2048
#define HH 16
#define DD 64
#define HID 1024
#define NTOK (BB * SS)
#define LOG2E 1.4426950408889634f
#define QSCALE (0.125f * LOG2E)
#define MASKADD (-10000.0f * LOG2E)

// -------- scratch (allocation-free __device__ globals) --------
__device__ __half g_x[(size_t)NTOK * HID];               // x, fp16
__device__ __half g_Wth[(size_t)3 * HID * HID];          // W^T [n][k] hi
__device__ __half g_Wtl[(size_t)3 * HID * HID];          // W^T [n][k] lo (residual)
__device__ __half g_Qh[(size_t)NTOK * HID];              // [b][h][s][d]
__device__ __half g_Kh[(size_t)NTOK * HID];
__device__ __half g_Vh[(size_t)NTOK * HID];

// ===================== helpers =====================
__device__ __forceinline__ uint32_t smem_u32(const void* p) {
    uint32_t a;
    asm("{ .reg .u64 t; cvta.to.shared.u64 t, %1; cvt.u32.u64 %0, t; }" : "=r"(a) : "l"(p));
    return a;
}
__device__ __forceinline__ uint32_t sw128(uint32_t o) { return o ^ ((o >> 3) & 0x70); }

__device__ __forceinline__ void ldsm4(uint32_t r[4], uint32_t addr) {
    asm volatile("ldmatrix.sync.aligned.m8n8.x4.shared.b16 {%0,%1,%2,%3}, [%4];"
                 : "=r"(r[0]), "=r"(r[1]), "=r"(r[2]), "=r"(r[3]) : "r"(addr));
}
__device__ __forceinline__ void ldsm4t(uint32_t r[4], uint32_t addr) {
    asm volatile("ldmatrix.sync.aligned.m8n8.x4.trans.shared.b16 {%0,%1,%2,%3}, [%4];"
                 : "=r"(r[0]), "=r"(r[1]), "=r"(r[2]), "=r"(r[3]) : "r"(addr));
}
// fp16 MMA, f32 accumulate
__device__ __forceinline__ void mma16816(float c[4], const uint32_t a[4],
                                         uint32_t b0, uint32_t b1) {
    asm volatile(
        "mma.sync.aligned.m16n8k16.row.col.f32.f16.f16.f32 "
        "{%0,%1,%2,%3}, {%4,%5,%6,%7}, {%8,%9}, {%0,%1,%2,%3};"
        : "+f"(c[0]), "+f"(c[1]), "+f"(c[2]), "+f"(c[3])
        : "r"(a[0]), "r"(a[1]), "r"(a[2]), "r"(a[3]), "r"(b0), "r"(b1));
}
// pack RN-fp16 pair: e0 -> low half, e1 -> high half
__device__ __forceinline__ uint32_t packh(float e0, float e1) {
    __half2 h = __floats2half2_rn(e0, e1);
    return *reinterpret_cast<uint32_t*>(&h);
}
// FFMA-only exp2
__device__ __forceinline__ float exp2p(float x) {
    x = fmaxf(x, -100.0f);
    float t = x + 12582912.0f;
    int   k = __float_as_int(t) - 0x4B400000;
    float f = x - (t - 12582912.0f);
    float r = 1.3333558146428443e-3f;
    r = fmaf(r, f, 9.618129107628477e-3f);
    r = fmaf(r, f, 5.550410866482158e-2f);
    r = fmaf(r, f, 2.402265069591007e-1f);
    r = fmaf(r, f, 6.931471805599453e-1f);
    r = fmaf(r, f, 1.0f);
    return r * __int_as_float(0x3F800000 + (k << 23));
}
__device__ __forceinline__ void cpa16(uint32_t s, const void* g) {
    asm volatile("cp.async.cg.shared.global [%0], [%1], 16;" :: "r"(s), "l"(g));
}
__device__ __forceinline__ void cpa4(uint32_t s, const void* g) {
    asm volatile("cp.async.ca.shared.global [%0], [%1], 4;" :: "r"(s), "l"(g));
}
#define CPA_COMMIT() asm volatile("cp.async.commit_group;")
#define CPA_WAIT2()  asm volatile("cp.async.wait_group 2;")
#define CPA_WAIT1()  asm volatile("cp.async.wait_group 1;")
#define CPA_WAIT0()  asm volatile("cp.async.wait_group 0;")

// ===================== prep kernels =====================
__global__ void conv_x(const float* __restrict__ x) {
    int i = blockIdx.x * 256 + threadIdx.x;
    g_x[i] = __float2half_rn(x[i]);
}

__global__ void conv_w(const float* __restrict__ Wq, const float* __restrict__ Wk,
                       const float* __restrict__ Wv) {
    __shared__ float t[32][33];
    int z = blockIdx.z;
    const float* W = (z == 0) ? Wq : (z == 1) ? Wk : Wv;
    int tx = threadIdx.x, ty = threadIdx.y;
    t[ty][tx] = W[(size_t)(blockIdx.y * 32 + ty) * HID + blockIdx.x * 32 + tx];
    __syncthreads();
    int n = blockIdx.x * 32 + ty;
    int k = blockIdx.y * 32 + tx;
    float v = t[tx][ty];
    __half h = __float2half_rn(v);
    size_t o = (size_t)z * HID * HID + (size_t)n * HID + k;
    g_Wth[o] = h;
    g_Wtl[o] = __float2half_rn(v - __half2float(h));
}

// ===================== QKV GEMM (fp16 2-term: x*Wh + x*Wl) =====================
// BM=128, BN=64, BK=64. stage: A@0(16K) Bh@16K(8K) Bl@24K(8K) = 32K; 3 stages.
#define GSTAGE 32768
#define GSMEM  (3 * GSTAGE)      // 98304
#define NCHUNK 16

__global__ __launch_bounds__(256, 2)
void qkv_gemm_mma(const float* __restrict__ bq, const float* __restrict__ bk,
                  const float* __restrict__ bv) {
    extern __shared__ __align__(1024) char sm[];
    const int tid = threadIdx.x, lane = tid & 31, wid = tid >> 5;
    const int wm = wid & 3, wn = wid >> 2;
    const int z = blockIdx.z;
    const int m0 = blockIdx.y * 128;
    const int n0 = blockIdx.x * 64;

    const __half* Wh = g_Wth + (size_t)z * HID * HID;
    const __half* Wl = g_Wtl + (size_t)z * HID * HID;
    const float* bias = (z == 0) ? bq : (z == 1) ? bk : bv;
    const uint32_t smb = smem_u32(sm);

    auto issue = [&](int c, int s) {
        const uint32_t sb = smb + s * GSTAGE;
        const int k0 = c * 64;
#pragma unroll
        for (int j = 0; j < 4; j++) {               // A: 128 rows x 8 x 16B
            int idx = tid + 256 * j;
            int row = idx >> 3, ch = idx & 7;
            uint32_t so = sw128((uint32_t)(row * 128 + ch * 16));
            cpa16(sb + so, g_x + (size_t)(m0 + row) * HID + k0 + ch * 8);
        }
#pragma unroll
        for (int j = 0; j < 2; j++) {               // B: 64 rows x 8 x 16B, hi+lo
            int idx = tid + 256 * j;
            int row = idx >> 3, ch = idx & 7;
            uint32_t so = sw128((uint32_t)(row * 128 + ch * 16));
            size_t gb = (size_t)(n0 + row) * HID + k0 + ch * 8;
            cpa16(sb + 16384 + so, Wh + gb);
            cpa16(sb + 24576 + so, Wl + gb);
        }
        CPA_COMMIT();
    };

    float acc[2][4][4];
#pragma unroll
    for (int i = 0; i < 2; i++)
#pragma unroll
        for (int j = 0; j < 4; j++)
#pragma unroll
            for (int v = 0; v < 4; v++) acc[i][j][v] = 0.f;

    issue(0, 0); issue(1, 1); issue(2, 2);

    // precomputed swizzled offsets (stage-invariant)
    uint32_t offA[4], offB[4];
    {
        const int rA = wm * 32 + (lane & 15);
        const int rB = wn * 32 + (lane & 15);
#pragma unroll
        for (int kk = 0; kk < 4; kk++) {
            const int cB = kk * 32 + (lane >> 4) * 16;
            offA[kk] = sw128((uint32_t)(rA * 128 + cB));
            offB[kk] = 16384 + sw128((uint32_t)(rB * 128 + cB));
        }
    }

    for (int c = 0; c < NCHUNK; c++) {
        const int s = c % 3;
        const uint32_t sb = smb + s * GSTAGE;
        if (c <= NCHUNK - 3) CPA_WAIT2();
        else if (c == NCHUNK - 2) CPA_WAIT1();
        else CPA_WAIT0();
        __syncthreads();

#pragma unroll
        for (int kk = 0; kk < 4; kk++) {
            const uint32_t aA = sb + offA[kk];
            const uint32_t aB = sb + offB[kk];
            uint32_t ah[2][4], bh[2][4], bl[2][4];
            ldsm4(ah[0], aA);            ldsm4(ah[1], aA + 2048);
            ldsm4(bh[0], aB);            ldsm4(bh[1], aB + 2048);
            ldsm4(bl[0], aB + 8192);     ldsm4(bl[1], aB + 10240);
#pragma unroll
            for (int g = 0; g < 2; g++) {
#pragma unroll
                for (int mi = 0; mi < 2; mi++) {
                    mma16816(acc[mi][2 * g],     ah[mi], bh[g][0], bh[g][2]);
                    mma16816(acc[mi][2 * g + 1], ah[mi], bh[g][1], bh[g][3]);
                    mma16816(acc[mi][2 * g],     ah[mi], bl[g][0], bl[g][2]);
                    mma16816(acc[mi][2 * g + 1], ah[mi], bl[g][1], bl[g][3]);
                }
            }
        }
        __syncthreads();
        if (c + 3 < NCHUNK) issue(c + 3, (c + 3) % 3);
    }

    // epilogue: bias (+Q scale), store fp16 [b,h,s,d]
    __half* outh = (z == 0) ? g_Qh : (z == 1) ? g_Kh : g_Vh;
    const float sc = (z == 0) ? QSCALE : 1.0f;
#pragma unroll
    for (int mi = 0; mi < 2; mi++) {
        int r0 = m0 + wm * 32 + mi * 16 + (lane >> 2);
#pragma unroll
        for (int nj = 0; nj < 4; nj++) {
            int col = n0 + wn * 32 + nj * 8 + 2 * (lane & 3);
            float b0v = __ldg(&bias[col]), b1v = __ldg(&bias[col + 1]);
#pragma unroll
            for (int half_ = 0; half_ < 2; half_++) {
                int r = r0 + half_ * 8;
                float v0 = (acc[mi][nj][half_ * 2 + 0] + b0v) * sc;
                float v1 = (acc[mi][nj][half_ * 2 + 1] + b1v) * sc;
                size_t off = (((size_t)((r >> 11) * HH + (col >> 6)) * SS +
                               (r & (SS - 1))) * DD) + (col & (DD - 1));
                *(uint32_t*)(outh + off) = packh(v0, v1);
            }
        }
    }
}

// ===================== flash attention (fp16: 1-term QK, 1-term PV) ================
// CTA: 128 q rows, 8 warps. 64 keys/chunk, 32 chunks.
// stage s@s*16384: Kh@0(8K) Vh@8192. mask ints @49152+s*256.
#define ASTAGE 16384
#define AADDER (3 * ASTAGE)          // 49152
#define ASMEM  (AADDER + 3 * 256)    // 49920
#define ACH 32

__global__ __launch_bounds__(256, 2)
void attn_mma(const int* __restrict__ mask, float* __restrict__ out) {
    extern __shared__ __align__(1024) char sm[];
    const int tid = threadIdx.x, lane = tid & 31, wid = tid >> 5;
    const int q0 = blockIdx.x * 128;
    const int h = blockIdx.y, b = blockIdx.z;
    const size_t hb = (size_t)(b * HH + h) * SS * DD;
    const uint32_t smb = smem_u32(sm);

    // ---- prologue: stage Q, read A-frags ----
#pragma unroll
    for (int j = 0; j < 4; j++) {
        int idx = tid + 256 * j;
        int row = idx >> 3, ch = idx & 7;
        uint32_t so = sw128((uint32_t)(row * 128 + ch * 16));
        *(uint4*)(sm + so) = *(const uint4*)(g_Qh + hb + (size_t)(q0 + row) * DD + ch * 8);
    }
    __syncthreads();
    uint32_t qh[4][4];
    {
        int r = wid * 16 + (lane & 15);
#pragma unroll
        for (int kk = 0; kk < 4; kk++) {
            int cB = kk * 32 + (lane >> 4) * 16;
            ldsm4(qh[kk], smb + sw128((uint32_t)(r * 128 + cB)));
        }
    }
    __syncthreads();

    auto issue = [&](int c, int s) {
        const uint32_t sb = smb + s * ASTAGE;
        const int c0 = c * 64;
#pragma unroll
        for (int j = 0; j < 2; j++) {
            int idx = tid + 256 * j;
            int row = idx >> 3, ch = idx & 7;
            uint32_t so = sw128((uint32_t)(row * 128 + ch * 16));
            size_t g = hb + (size_t)(c0 + row) * DD + ch * 8;
            cpa16(sb + so,        g_Kh + g);
            cpa16(sb + 8192 + so, g_Vh + g);
        }
        if (tid < 64) cpa4(smb + AADDER + s * 256 + tid * 4, mask + b * SS + c0 + tid);
        CPA_COMMIT();
    };

    float ctx[8][4];
#pragma unroll
    for (int i = 0; i < 8; i++)
#pragma unroll
        for (int j = 0; j < 4; j++) ctx[i][j] = 0.f;
    float l0s = 0.f, l1s = 0.f;

    issue(0, 0); issue(1, 1); issue(2, 2);

    // precomputed swizzled offsets (stage-invariant)
    uint32_t offK[4], offV[4];
    {
        const int rk = lane & 15;
#pragma unroll
        for (int i = 0; i < 4; i++) {
            const int cB = i * 32 + (lane >> 4) * 16;
            offK[i] = sw128((uint32_t)(rk * 128 + cB));
            offV[i] = 8192 + sw128((uint32_t)(rk * 128 + cB));
        }
    }
    const int kcol = 2 * (lane & 3);

    for (int c = 0; c < ACH; c++) {
        const int s = c % 3;
        const uint32_t sb = smb + s * ASTAGE;
        if (c <= ACH - 3) CPA_WAIT2();
        else if (c == ACH - 2) CPA_WAIT1();
        else CPA_WAIT0();
        __syncthreads();

        // ---- S = Q K^T (1-term fp16) ----
        float sacc[8][4];
#pragma unroll
        for (int i = 0; i < 8; i++)
#pragma unroll
            for (int j = 0; j < 4; j++) sacc[i][j] = 0.f;

#pragma unroll
        for (int kk = 0; kk < 4; kk++) {
            const uint32_t ka = sb + offK[kk];
#pragma unroll
            for (int g = 0; g < 4; g++) {
                uint32_t kh[4];
                ldsm4(kh, ka + g * 2048);
                mma16816(sacc[2 * g],     qh[kk], kh[0], kh[2]);
                mma16816(sacc[2 * g + 1], qh[kk], kh[1], kh[3]);
            }
        }

        // ---- softmax numerator (fixed base), pack P as RN fp16 ----
        const int* madd = (const int*)(sm + AADDER + s * 256);
        uint32_t ph[4][4];
#pragma unroll
        for (int kg = 0; kg < 4; kg++) {
            const float* s0 = sacc[2 * kg];
            const float* s1 = sacc[2 * kg + 1];
            float a0 = madd[kg * 16 + kcol]         ? 0.f : MASKADD;
            float a1 = madd[kg * 16 + kcol + 1]     ? 0.f : MASKADD;
            float a2 = madd[kg * 16 + 8 + kcol]     ? 0.f : MASKADD;
            float a3 = madd[kg * 16 + 8 + kcol + 1] ? 0.f : MASKADD;
            float p00 = exp2p(s0[0] + a0), p01 = exp2p(s0[1] + a1);
            float p02 = exp2p(s0[2] + a0), p03 = exp2p(s0[3] + a1);
            float p10 = exp2p(s1[0] + a2), p11 = exp2p(s1[1] + a3);
            float p12 = exp2p(s1[2] + a2), p13 = exp2p(s1[3] + a3);
            l0s += (p00 + p01) + (p10 + p11);
            l1s += (p02 + p03) + (p12 + p13);
            ph[kg][0] = packh(p00, p01);
            ph[kg][1] = packh(p02, p03);
            ph[kg][2] = packh(p10, p11);
            ph[kg][3] = packh(p12, p13);
        }

        // ---- ctx += P V (1-term fp16) ----
#pragma unroll
        for (int dg = 0; dg < 4; dg++) {
            const uint32_t va = sb + offV[dg];
#pragma unroll
            for (int kg = 0; kg < 4; kg++) {
                uint32_t vh[4];
                ldsm4t(vh, va + kg * 2048);
                mma16816(ctx[2 * dg],     ph[kg], vh[0], vh[1]);
                mma16816(ctx[2 * dg + 1], ph[kg], vh[2], vh[3]);
            }
        }
        __syncthreads();
        if (c + 3 < ACH) issue(c + 3, (c + 3) % 3);
    }

    // ---- l reduction across the quad, write out [b, s, h*64 + d] ----
    l0s += __shfl_xor_sync(0xFFFFFFFFu, l0s, 1);
    l0s += __shfl_xor_sync(0xFFFFFFFFu, l0s, 2);
    l1s += __shfl_xor_sync(0xFFFFFFFFu, l1s, 1);
    l1s += __shfl_xor_sync(0xFFFFFFFFu, l1s, 2);
    const float inv0 = 1.0f / l0s, inv1 = 1.0f / l1s;
    const int r0 = q0 + wid * 16 + (lane >> 2);
    const int dbase = 2 * (lane & 3);
#pragma unroll
    for (int nj = 0; nj < 8; nj++) {
        int d = nj * 8 + dbase;
        float2 v0 = make_float2(ctx[nj][0] * inv0, ctx[nj][1] * inv0);
        float2 v1 = make_float2(ctx[nj][2] * inv1, ctx[nj][3] * inv1);
        *(float2*)&out[(size_t)(b * SS + r0) * HID + h * DD + d] = v0;
        *(float2*)&out[(size_t)(b * SS + r0 + 8) * HID + h * DD + d] = v1;
    }
}

// ===================== launch =====================
extern "C" void kernel_launch(void* const* d_in, const int* in_sizes, int n_in,
                              void* d_out, int out_size) {
    const float* x    = (const float*)d_in[0];
    const int*   mask = (const int*)d_in[1];
    const float* Wq   = (const float*)d_in[2];
    const float* bq   = (const float*)d_in[3];
    const float* Wk   = (const float*)d_in[4];
    const float* bk   = (const float*)d_in[5];
    const float* Wv   = (const float*)d_in[6];
    const float* bv   = (const float*)d_in[7];
    float* out = (float*)d_out;

    static int attr_done = 0;
    if (!attr_done) {
        cudaFuncSetAttribute(qkv_gemm_mma,
                             cudaFuncAttributeMaxDynamicSharedMemorySize, GSMEM);
        cudaFuncSetAttribute(attn_mma,
                             cudaFuncAttributeMaxDynamicSharedMemorySize, ASMEM);
        attr_done = 1;
    }

    conv_x<<<(NTOK * HID) / 256, 256>>>(x);
    dim3 wgrid(HID / 32, HID / 32, 3);
    conv_w<<<wgrid, dim3(32, 32)>>>(Wq, Wk, Wv);

    dim3 ggrid(HID / 64, NTOK / 128, 3);
    qkv_gemm_mma<<<ggrid, 256, GSMEM>>>(bq, bk, bv);

    dim3 agrid(SS / 128, HH, BB);
    attn_mma<<<agrid, 256, ASMEM>>>(mask, out);
}

// round 12
// speedup vs baseline: 2.4919x; 1.2981x over previous
#include <cuda_runtime.h>
#include <cuda_fp16.h>
#include <math.h>
#include <stdint.h>

#define BB 2
#define SS 2048
#define HH 16
#define DD 64
#define HID 1024
#define NTOK (BB * SS)
#define LOG2E 1.4426950408889634f
#define QSCALE (0.125f * LOG2E)
#define MASKADD (-64.0f)     // log2-domain; exp2(-64) == 0 in fp16, ~5e-20 in fp32

// -------- scratch (allocation-free __device__ globals) --------
__device__ __half g_x[(size_t)NTOK * HID];               // x, fp16
__device__ __half g_Wth[(size_t)3 * HID * HID];          // W^T [n][k], fp16
__device__ __half g_Qh[(size_t)NTOK * HID];              // [b][h][s][d]
__device__ __half g_Kh[(size_t)NTOK * HID];
__device__ __half g_Vh[(size_t)NTOK * HID];

// ===================== helpers =====================
__device__ __forceinline__ uint32_t smem_u32(const void* p) {
    uint32_t a;
    asm("{ .reg .u64 t; cvta.to.shared.u64 t, %1; cvt.u32.u64 %0, t; }" : "=r"(a) : "l"(p));
    return a;
}
__device__ __forceinline__ uint32_t sw128(uint32_t o) { return o ^ ((o >> 3) & 0x70); }

__device__ __forceinline__ void ldsm4(uint32_t r[4], uint32_t addr) {
    asm volatile("ldmatrix.sync.aligned.m8n8.x4.shared.b16 {%0,%1,%2,%3}, [%4];"
                 : "=r"(r[0]), "=r"(r[1]), "=r"(r[2]), "=r"(r[3]) : "r"(addr));
}
__device__ __forceinline__ void ldsm4t(uint32_t r[4], uint32_t addr) {
    asm volatile("ldmatrix.sync.aligned.m8n8.x4.trans.shared.b16 {%0,%1,%2,%3}, [%4];"
                 : "=r"(r[0]), "=r"(r[1]), "=r"(r[2]), "=r"(r[3]) : "r"(addr));
}
// fp16 MMA, f32 accumulate
__device__ __forceinline__ void mma16816(float c[4], const uint32_t a[4],
                                         uint32_t b0, uint32_t b1) {
    asm volatile(
        "mma.sync.aligned.m16n8k16.row.col.f32.f16.f16.f32 "
        "{%0,%1,%2,%3}, {%4,%5,%6,%7}, {%8,%9}, {%0,%1,%2,%3};"
        : "+f"(c[0]), "+f"(c[1]), "+f"(c[2]), "+f"(c[3])
        : "r"(a[0]), "r"(a[1]), "r"(a[2]), "r"(a[3]), "r"(b0), "r"(b1));
}
// pack RN-fp16 pair: e0 -> low half, e1 -> high half
__device__ __forceinline__ uint32_t packh(float e0, float e1) {
    __half2 h = __floats2half2_rn(e0, e1);
    return *reinterpret_cast<uint32_t*>(&h);
}
// FFMA-only exp2 (no clamp: x >= ~-84 by construction)
__device__ __forceinline__ float exp2p(float x) {
    float t = x + 12582912.0f;
    int   k = __float_as_int(t) - 0x4B400000;
    float f = x - (t - 12582912.0f);
    float r = 1.3333558146428443e-3f;
    r = fmaf(r, f, 9.618129107628477e-3f);
    r = fmaf(r, f, 5.550410866482158e-2f);
    r = fmaf(r, f, 2.402265069591007e-1f);
    r = fmaf(r, f, 6.931471805599453e-1f);
    r = fmaf(r, f, 1.0f);
    return r * __int_as_float(0x3F800000 + (k << 23));
}
__device__ __forceinline__ void cpa16(uint32_t s, const void* g) {
    asm volatile("cp.async.cg.shared.global [%0], [%1], 16;" :: "r"(s), "l"(g));
}
#define CPA_COMMIT() asm volatile("cp.async.commit_group;")
#define CPA_WAIT2()  asm volatile("cp.async.wait_group 2;")
#define CPA_WAIT1()  asm volatile("cp.async.wait_group 1;")
#define CPA_WAIT0()  asm volatile("cp.async.wait_group 0;")

#define ONESF16X2 0x3C003C00u     // half2(1.0, 1.0)

// ===================== prep kernels =====================
__global__ void conv_x(const float* __restrict__ x) {
    int i = blockIdx.x * 256 + threadIdx.x;
    g_x[i] = __float2half_rn(x[i]);
}

__global__ void conv_w(const float* __restrict__ Wq, const float* __restrict__ Wk,
                       const float* __restrict__ Wv) {
    __shared__ float t[32][33];
    int z = blockIdx.z;
    const float* W = (z == 0) ? Wq : (z == 1) ? Wk : Wv;
    int tx = threadIdx.x, ty = threadIdx.y;
    t[ty][tx] = W[(size_t)(blockIdx.y * 32 + ty) * HID + blockIdx.x * 32 + tx];
    __syncthreads();
    int n = blockIdx.x * 32 + ty;
    int k = blockIdx.y * 32 + tx;
    g_Wth[(size_t)z * HID * HID + (size_t)n * HID + k] = __float2half_rn(t[tx][ty]);
}

// ===================== QKV GEMM (single-term fp16: x*Wh) =====================
// BM=128, BN=64, BK=64. stage: A@0(16K) Bh@16K(8K) = 24K; 3 stages.
#define GSTAGE 24576
#define GSMEM  (3 * GSTAGE)      // 73728
#define NCHUNK 16

__global__ __launch_bounds__(256, 2)
void qkv_gemm_mma(const float* __restrict__ bq, const float* __restrict__ bk,
                  const float* __restrict__ bv) {
    extern __shared__ __align__(1024) char sm[];
    const int tid = threadIdx.x, lane = tid & 31, wid = tid >> 5;
    const int wm = wid & 3, wn = wid >> 2;
    const int z = blockIdx.z;
    const int m0 = blockIdx.y * 128;
    const int n0 = blockIdx.x * 64;

    const __half* Wh = g_Wth + (size_t)z * HID * HID;
    const float* bias = (z == 0) ? bq : (z == 1) ? bk : bv;
    const uint32_t smb = smem_u32(sm);

    auto issue = [&](int c, int s) {
        const uint32_t sb = smb + s * GSTAGE;
        const int k0 = c * 64;
#pragma unroll
        for (int j = 0; j < 4; j++) {               // A: 128 rows x 8 x 16B
            int idx = tid + 256 * j;
            int row = idx >> 3, ch = idx & 7;
            uint32_t so = sw128((uint32_t)(row * 128 + ch * 16));
            cpa16(sb + so, g_x + (size_t)(m0 + row) * HID + k0 + ch * 8);
        }
#pragma unroll
        for (int j = 0; j < 2; j++) {               // B: 64 rows x 8 x 16B
            int idx = tid + 256 * j;
            int row = idx >> 3, ch = idx & 7;
            uint32_t so = sw128((uint32_t)(row * 128 + ch * 16));
            cpa16(sb + 16384 + so, Wh + (size_t)(n0 + row) * HID + k0 + ch * 8);
        }
        CPA_COMMIT();
    };

    float acc[2][4][4];
#pragma unroll
    for (int i = 0; i < 2; i++)
#pragma unroll
        for (int j = 0; j < 4; j++)
#pragma unroll
            for (int v = 0; v < 4; v++) acc[i][j][v] = 0.f;

    issue(0, 0); issue(1, 1); issue(2, 2);

    // precomputed swizzled offsets (stage-invariant)
    uint32_t offA[4], offB[4];
    {
        const int rA = wm * 32 + (lane & 15);
        const int rB = wn * 32 + (lane & 15);
#pragma unroll
        for (int kk = 0; kk < 4; kk++) {
            const int cB = kk * 32 + (lane >> 4) * 16;
            offA[kk] = sw128((uint32_t)(rA * 128 + cB));
            offB[kk] = 16384 + sw128((uint32_t)(rB * 128 + cB));
        }
    }

    for (int c = 0; c < NCHUNK; c++) {
        const int s = c % 3;
        const uint32_t sb = smb + s * GSTAGE;
        if (c <= NCHUNK - 3) CPA_WAIT2();
        else if (c == NCHUNK - 2) CPA_WAIT1();
        else CPA_WAIT0();
        __syncthreads();

#pragma unroll
        for (int kk = 0; kk < 4; kk++) {
            const uint32_t aA = sb + offA[kk];
            const uint32_t aB = sb + offB[kk];
            uint32_t ah[2][4], bh[2][4];
            ldsm4(ah[0], aA);            ldsm4(ah[1], aA + 2048);
            ldsm4(bh[0], aB);            ldsm4(bh[1], aB + 2048);
#pragma unroll
            for (int g = 0; g < 2; g++) {
#pragma unroll
                for (int mi = 0; mi < 2; mi++) {
                    mma16816(acc[mi][2 * g],     ah[mi], bh[g][0], bh[g][2]);
                    mma16816(acc[mi][2 * g + 1], ah[mi], bh[g][1], bh[g][3]);
                }
            }
        }
        __syncthreads();
        if (c + 3 < NCHUNK) issue(c + 3, (c + 3) % 3);
    }

    // epilogue: bias (+Q scale), store fp16 [b,h,s,d]
    __half* outh = (z == 0) ? g_Qh : (z == 1) ? g_Kh : g_Vh;
    const float sc = (z == 0) ? QSCALE : 1.0f;
#pragma unroll
    for (int mi = 0; mi < 2; mi++) {
        int r0 = m0 + wm * 32 + mi * 16 + (lane >> 2);
#pragma unroll
        for (int nj = 0; nj < 4; nj++) {
            int col = n0 + wn * 32 + nj * 8 + 2 * (lane & 3);
            float b0v = __ldg(&bias[col]), b1v = __ldg(&bias[col + 1]);
#pragma unroll
            for (int half_ = 0; half_ < 2; half_++) {
                int r = r0 + half_ * 8;
                float v0 = (acc[mi][nj][half_ * 2 + 0] + b0v) * sc;
                float v1 = (acc[mi][nj][half_ * 2 + 1] + b1v) * sc;
                size_t off = (((size_t)((r >> 11) * HH + (col >> 6)) * SS +
                               (r & (SS - 1))) * DD) + (col & (DD - 1));
                *(uint32_t*)(outh + off) = packh(v0, v1);
            }
        }
    }
}

// ===================== flash attention (fp16, l-sum via ones-MMA) ==================
// CTA: 128 q rows, 8 warps. 64 keys/chunk, 32 chunks.
// stage s@s*16384: Kh@0(8K) Vh@8192. adder floats (all 2048 keys) @49152, 8KB.
#define ASTAGE 16384
#define AADDER (3 * ASTAGE)          // 49152
#define ASMEM  (AADDER + SS * 4)     // 57344
#define ACH 32

__global__ __launch_bounds__(256, 2)
void attn_mma(const int* __restrict__ mask, float* __restrict__ out) {
    extern __shared__ __align__(1024) char sm[];
    const int tid = threadIdx.x, lane = tid & 31, wid = tid >> 5;
    const int q0 = blockIdx.x * 128;
    const int h = blockIdx.y, b = blockIdx.z;
    const size_t hb = (size_t)(b * HH + h) * SS * DD;
    const uint32_t smb = smem_u32(sm);

    // ---- prologue: stage Q, precompute all mask adders, read Q frags ----
#pragma unroll
    for (int j = 0; j < 4; j++) {
        int idx = tid + 256 * j;
        int row = idx >> 3, ch = idx & 7;
        uint32_t so = sw128((uint32_t)(row * 128 + ch * 16));
        *(uint4*)(sm + so) = *(const uint4*)(g_Qh + hb + (size_t)(q0 + row) * DD + ch * 8);
    }
#pragma unroll
    for (int j = 0; j < SS / 256; j++) {
        int i = tid + 256 * j;
        ((float*)(sm + AADDER))[i] = mask[b * SS + i] ? 0.f : MASKADD;
    }
    __syncthreads();
    uint32_t qh[4][4];
    {
        int r = wid * 16 + (lane & 15);
#pragma unroll
        for (int kk = 0; kk < 4; kk++) {
            int cB = kk * 32 + (lane >> 4) * 16;
            ldsm4(qh[kk], smb + sw128((uint32_t)(r * 128 + cB)));
        }
    }
    __syncthreads();

    auto issue = [&](int c, int s) {
        const uint32_t sb = smb + s * ASTAGE;
        const int c0 = c * 64;
#pragma unroll
        for (int j = 0; j < 2; j++) {
            int idx = tid + 256 * j;
            int row = idx >> 3, ch = idx & 7;
            uint32_t so = sw128((uint32_t)(row * 128 + ch * 16));
            size_t g = hb + (size_t)(c0 + row) * DD + ch * 8;
            cpa16(sb + so,        g_Kh + g);
            cpa16(sb + 8192 + so, g_Vh + g);
        }
        CPA_COMMIT();
    };

    float ctx[8][4];
#pragma unroll
    for (int i = 0; i < 8; i++)
#pragma unroll
        for (int j = 0; j < 4; j++) ctx[i][j] = 0.f;
    float lacc[4] = {0.f, 0.f, 0.f, 0.f};    // l-sums via ones-MMA

    issue(0, 0); issue(1, 1); issue(2, 2);

    // precomputed swizzled offsets (stage-invariant)
    uint32_t offK[4], offV[4];
    {
        const int rk = lane & 15;
#pragma unroll
        for (int i = 0; i < 4; i++) {
            const int cB = i * 32 + (lane >> 4) * 16;
            offK[i] = sw128((uint32_t)(rk * 128 + cB));
            offV[i] = 8192 + sw128((uint32_t)(rk * 128 + cB));
        }
    }
    const int kcol = 2 * (lane & 3);

    for (int c = 0; c < ACH; c++) {
        const int s = c % 3;
        const uint32_t sb = smb + s * ASTAGE;
        if (c <= ACH - 3) CPA_WAIT2();
        else if (c == ACH - 2) CPA_WAIT1();
        else CPA_WAIT0();
        __syncthreads();

        // ---- S = Q K^T (1-term fp16) ----
        float sacc[8][4];
#pragma unroll
        for (int i = 0; i < 8; i++)
#pragma unroll
            for (int j = 0; j < 4; j++) sacc[i][j] = 0.f;

#pragma unroll
        for (int kk = 0; kk < 4; kk++) {
            const uint32_t ka = sb + offK[kk];
#pragma unroll
            for (int g = 0; g < 4; g++) {
                uint32_t kh[4];
                ldsm4(kh, ka + g * 2048);
                mma16816(sacc[2 * g],     qh[kk], kh[0], kh[2]);
                mma16816(sacc[2 * g + 1], qh[kk], kh[1], kh[3]);
            }
        }

        // ---- softmax numerator (fixed base), pack P as RN fp16 ----
        const float* madd = (const float*)(sm + AADDER) + c * 64;
        uint32_t ph[4][4];
#pragma unroll
        for (int kg = 0; kg < 4; kg++) {
            const float* s0 = sacc[2 * kg];
            const float* s1 = sacc[2 * kg + 1];
            float a0 = madd[kg * 16 + kcol];
            float a1 = madd[kg * 16 + kcol + 1];
            float a2 = madd[kg * 16 + 8 + kcol];
            float a3 = madd[kg * 16 + 8 + kcol + 1];
            float p00 = exp2p(s0[0] + a0), p01 = exp2p(s0[1] + a1);
            float p02 = exp2p(s0[2] + a0), p03 = exp2p(s0[3] + a1);
            float p10 = exp2p(s1[0] + a2), p11 = exp2p(s1[1] + a3);
            float p12 = exp2p(s1[2] + a2), p13 = exp2p(s1[3] + a3);
            ph[kg][0] = packh(p00, p01);
            ph[kg][1] = packh(p02, p03);
            ph[kg][2] = packh(p10, p11);
            ph[kg][3] = packh(p12, p13);
        }

        // ---- l += P @ ones (4 MMAs replace 32 FADDs + end shfl tree) ----
#pragma unroll
        for (int kg = 0; kg < 4; kg++)
            mma16816(lacc, ph[kg], ONESF16X2, ONESF16X2);

        // ---- ctx += P V (1-term fp16) ----
#pragma unroll
        for (int dg = 0; dg < 4; dg++) {
            const uint32_t va = sb + offV[dg];
#pragma unroll
            for (int kg = 0; kg < 4; kg++) {
                uint32_t vh[4];
                ldsm4t(vh, va + kg * 2048);
                mma16816(ctx[2 * dg],     ph[kg], vh[0], vh[1]);
                mma16816(ctx[2 * dg + 1], ph[kg], vh[2], vh[3]);
            }
        }
        __syncthreads();
        if (c + 3 < ACH) issue(c + 3, (c + 3) % 3);
    }

    // ---- write out [b, s, h*64 + d]; l fully reduced in lacc ----
    const float inv0 = 1.0f / lacc[0], inv1 = 1.0f / lacc[2];
    const int r0 = q0 + wid * 16 + (lane >> 2);
    const int dbase = 2 * (lane & 3);
#pragma unroll
    for (int nj = 0; nj < 8; nj++) {
        int d = nj * 8 + dbase;
        float2 v0 = make_float2(ctx[nj][0] * inv0, ctx[nj][1] * inv0);
        float2 v1 = make_float2(ctx[nj][2] * inv1, ctx[nj][3] * inv1);
        *(float2*)&out[(size_t)(b * SS + r0) * HID + h * DD + d] = v0;
        *(float2*)&out[(size_t)(b * SS + r0 + 8) * HID + h * DD + d] = v1;
    }
}

// ===================== launch =====================
extern "C" void kernel_launch(void* const* d_in, const int* in_sizes, int n_in,
                              void* d_out, int out_size) {
    const float* x    = (const float*)d_in[0];
    const int*   mask = (const int*)d_in[1];
    const float* Wq   = (const float*)d_in[2];
    const float* bq   = (const float*)d_in[3];
    const float* Wk   = (const float*)d_in[4];
    const float* bk   = (const float*)d_in[5];
    const float* Wv   = (const float*)d_in[6];
    const float* bv   = (const float*)d_in[7];
    float* out = (float*)d_out;

    static int attr_done = 0;
    if (!attr_done) {
        cudaFuncSetAttribute(qkv_gemm_mma,
                             cudaFuncAttributeMaxDynamicSharedMemorySize, GSMEM);
        cudaFuncSetAttribute(attn_mma,
                             cudaFuncAttributeMaxDynamicSharedMemorySize, ASMEM);
        attr_done = 1;
    }

    conv_x<<<(NTOK * HID) / 256, 256>>>(x);
    dim3 wgrid(HID / 32, HID / 32, 3);
    conv_w<<<wgrid, dim3(32, 32)>>>(Wq, Wk, Wv);

    dim3 ggrid(HID / 64, NTOK / 128, 3);
    qkv_gemm_mma<<<ggrid, 256, GSMEM>>>(bq, bk, bv);

    dim3 agrid(SS / 128, HH, BB);
    attn_mma<<<agrid, 256, ASMEM>>>(mask, out);
}

// round 13
// speedup vs baseline: 2.6497x; 1.0633x over previous
#include <cuda_runtime.h>
#include <cuda_fp16.h>
#include <math.h>
#include <stdint.h>

#define BB 2
#define SS 2048
#define HH 16
#define DD 64
#define HID 1024
#define NTOK (BB * SS)
#define LOG2E 1.4426950408889634f
#define QSCALE (0.125f * LOG2E)
#define MASKADD (-64.0f)     // log2-domain; exp2(-64) == 0 in fp16

// -------- scratch (allocation-free __device__ globals) --------
__device__ __half g_x[(size_t)NTOK * HID];               // x, fp16
__device__ __half g_Wth[(size_t)3 * HID * HID];          // W^T [n][k], fp16
__device__ __half g_Qh[(size_t)NTOK * HID];              // [b][h][s][d]
__device__ __half g_Kh[(size_t)NTOK * HID];
__device__ __half g_Vh[(size_t)NTOK * HID];

// ===================== helpers =====================
__device__ __forceinline__ uint32_t smem_u32(const void* p) {
    uint32_t a;
    asm("{ .reg .u64 t; cvta.to.shared.u64 t, %1; cvt.u32.u64 %0, t; }" : "=r"(a) : "l"(p));
    return a;
}
__device__ __forceinline__ uint32_t sw128(uint32_t o) { return o ^ ((o >> 3) & 0x70); }

__device__ __forceinline__ void ldsm4(uint32_t r[4], uint32_t addr) {
    asm volatile("ldmatrix.sync.aligned.m8n8.x4.shared.b16 {%0,%1,%2,%3}, [%4];"
                 : "=r"(r[0]), "=r"(r[1]), "=r"(r[2]), "=r"(r[3]) : "r"(addr));
}
__device__ __forceinline__ void ldsm4t(uint32_t r[4], uint32_t addr) {
    asm volatile("ldmatrix.sync.aligned.m8n8.x4.trans.shared.b16 {%0,%1,%2,%3}, [%4];"
                 : "=r"(r[0]), "=r"(r[1]), "=r"(r[2]), "=r"(r[3]) : "r"(addr));
}
// fp16 MMA, f32 accumulate
__device__ __forceinline__ void mma16816(float c[4], const uint32_t a[4],
                                         uint32_t b0, uint32_t b1) {
    asm volatile(
        "mma.sync.aligned.m16n8k16.row.col.f32.f16.f16.f32 "
        "{%0,%1,%2,%3}, {%4,%5,%6,%7}, {%8,%9}, {%0,%1,%2,%3};"
        : "+f"(c[0]), "+f"(c[1]), "+f"(c[2]), "+f"(c[3])
        : "r"(a[0]), "r"(a[1]), "r"(a[2]), "r"(a[3]), "r"(b0), "r"(b1));
}
// pack RN-fp16 pair: e0 -> low half, e1 -> high half
__device__ __forceinline__ uint32_t packh(float e0, float e1) {
    __half2 h = __floats2half2_rn(e0, e1);
    return *reinterpret_cast<uint32_t*>(&h);
}
// FFMA-only exp2, degree-3 economized (max rel err ~1.2e-4; P is fp16 anyway)
__device__ __forceinline__ float exp2p(float x) {
    float t = x + 12582912.0f;
    int   k = __float_as_int(t) - 0x4B400000;
    float f = x - (t - 12582912.0f);
    float r = 5.5504108664821580e-2f;
    r = fmaf(r, f, 2.4263096e-1f);
    r = fmaf(r, f, 6.9314718e-1f);
    r = fmaf(r, f, 9.9992490e-1f);
    return r * __int_as_float(0x3F800000 + (k << 23));
}
__device__ __forceinline__ void cpa16(uint32_t s, const void* g) {
    asm volatile("cp.async.cg.shared.global [%0], [%1], 16;" :: "r"(s), "l"(g));
}
#define CPA_COMMIT() asm volatile("cp.async.commit_group;")
#define CPA_WAIT2()  asm volatile("cp.async.wait_group 2;")
#define CPA_WAIT1()  asm volatile("cp.async.wait_group 1;")
#define CPA_WAIT0()  asm volatile("cp.async.wait_group 0;")

#define ONESF16X2 0x3C003C00u     // half2(1.0, 1.0)

// ===================== prep kernels =====================
__global__ void conv_x(const float* __restrict__ x) {
    int i = blockIdx.x * 256 + threadIdx.x;
    g_x[i] = __float2half_rn(x[i]);
}

__global__ void conv_w(const float* __restrict__ Wq, const float* __restrict__ Wk,
                       const float* __restrict__ Wv) {
    __shared__ float t[32][33];
    int z = blockIdx.z;
    const float* W = (z == 0) ? Wq : (z == 1) ? Wk : Wv;
    int tx = threadIdx.x, ty = threadIdx.y;
    t[ty][tx] = W[(size_t)(blockIdx.y * 32 + ty) * HID + blockIdx.x * 32 + tx];
    __syncthreads();
    int n = blockIdx.x * 32 + ty;
    int k = blockIdx.y * 32 + tx;
    g_Wth[(size_t)z * HID * HID + (size_t)n * HID + k] = __float2half_rn(t[tx][ty]);
}

// ===================== QKV GEMM (single-term fp16: x*Wh) =====================
// BM=128, BN=64, BK=64. stage: A@0(16K) Bh@16K(8K) = 24K; 3 stages.
#define GSTAGE 24576
#define GSMEM  (3 * GSTAGE)      // 73728
#define NCHUNK 16

__global__ __launch_bounds__(256, 2)
void qkv_gemm_mma(const float* __restrict__ bq, const float* __restrict__ bk,
                  const float* __restrict__ bv) {
    extern __shared__ __align__(1024) char sm[];
    const int tid = threadIdx.x, lane = tid & 31, wid = tid >> 5;
    const int wm = wid & 3, wn = wid >> 2;
    const int z = blockIdx.z;
    const int m0 = blockIdx.y * 128;
    const int n0 = blockIdx.x * 64;

    const __half* Wh = g_Wth + (size_t)z * HID * HID;
    const float* bias = (z == 0) ? bq : (z == 1) ? bk : bv;
    const uint32_t smb = smem_u32(sm);

    auto issue = [&](int c, int s) {
        const uint32_t sb = smb + s * GSTAGE;
        const int k0 = c * 64;
#pragma unroll
        for (int j = 0; j < 4; j++) {               // A: 128 rows x 8 x 16B
            int idx = tid + 256 * j;
            int row = idx >> 3, ch = idx & 7;
            uint32_t so = sw128((uint32_t)(row * 128 + ch * 16));
            cpa16(sb + so, g_x + (size_t)(m0 + row) * HID + k0 + ch * 8);
        }
#pragma unroll
        for (int j = 0; j < 2; j++) {               // B: 64 rows x 8 x 16B
            int idx = tid + 256 * j;
            int row = idx >> 3, ch = idx & 7;
            uint32_t so = sw128((uint32_t)(row * 128 + ch * 16));
            cpa16(sb + 16384 + so, Wh + (size_t)(n0 + row) * HID + k0 + ch * 8);
        }
        CPA_COMMIT();
    };

    float acc[2][4][4];
#pragma unroll
    for (int i = 0; i < 2; i++)
#pragma unroll
        for (int j = 0; j < 4; j++)
#pragma unroll
            for (int v = 0; v < 4; v++) acc[i][j][v] = 0.f;

    issue(0, 0); issue(1, 1); issue(2, 2);

    uint32_t offA[4], offB[4];
    {
        const int rA = wm * 32 + (lane & 15);
        const int rB = wn * 32 + (lane & 15);
#pragma unroll
        for (int kk = 0; kk < 4; kk++) {
            const int cB = kk * 32 + (lane >> 4) * 16;
            offA[kk] = sw128((uint32_t)(rA * 128 + cB));
            offB[kk] = 16384 + sw128((uint32_t)(rB * 128 + cB));
        }
    }

    for (int c = 0; c < NCHUNK; c++) {
        const int s = c % 3;
        const uint32_t sb = smb + s * GSTAGE;
        if (c <= NCHUNK - 3) CPA_WAIT2();
        else if (c == NCHUNK - 2) CPA_WAIT1();
        else CPA_WAIT0();
        __syncthreads();

#pragma unroll
        for (int kk = 0; kk < 4; kk++) {
            const uint32_t aA = sb + offA[kk];
            const uint32_t aB = sb + offB[kk];
            uint32_t ah[2][4], bh[2][4];
            ldsm4(ah[0], aA);            ldsm4(ah[1], aA + 2048);
            ldsm4(bh[0], aB);            ldsm4(bh[1], aB + 2048);
#pragma unroll
            for (int g = 0; g < 2; g++) {
#pragma unroll
                for (int mi = 0; mi < 2; mi++) {
                    mma16816(acc[mi][2 * g],     ah[mi], bh[g][0], bh[g][2]);
                    mma16816(acc[mi][2 * g + 1], ah[mi], bh[g][1], bh[g][3]);
                }
            }
        }
        __syncthreads();
        if (c + 3 < NCHUNK) issue(c + 3, (c + 3) % 3);
    }

    __half* outh = (z == 0) ? g_Qh : (z == 1) ? g_Kh : g_Vh;
    const float sc = (z == 0) ? QSCALE : 1.0f;
#pragma unroll
    for (int mi = 0; mi < 2; mi++) {
        int r0 = m0 + wm * 32 + mi * 16 + (lane >> 2);
#pragma unroll
        for (int nj = 0; nj < 4; nj++) {
            int col = n0 + wn * 32 + nj * 8 + 2 * (lane & 3);
            float b0v = __ldg(&bias[col]), b1v = __ldg(&bias[col + 1]);
#pragma unroll
            for (int half_ = 0; half_ < 2; half_++) {
                int r = r0 + half_ * 8;
                float v0 = (acc[mi][nj][half_ * 2 + 0] + b0v) * sc;
                float v1 = (acc[mi][nj][half_ * 2 + 1] + b1v) * sc;
                size_t off = (((size_t)((r >> 11) * HH + (col >> 6)) * SS +
                               (r & (SS - 1))) * DD) + (col & (DD - 1));
                *(uint32_t*)(outh + off) = packh(v0, v1);
            }
        }
    }
}

// ===================== flash attention =====================
// 128-key stages (K 16K + V 16K = 32K), 3 stages; two 64-key halves per stage.
// adder floats @98304 (8K), block flags @106496 (32 ints).
#define ASTAGE 32768
#define AADDER (3 * ASTAGE)              // 98304
#define AFLAGS (AADDER + SS * 4)         // 106496
#define ASMEM  (AFLAGS + 128)            // 106624
#define NPAIR 16

__global__ __launch_bounds__(256, 2)
void attn_mma(const int* __restrict__ mask, float* __restrict__ out) {
    extern __shared__ __align__(1024) char sm[];
    const int tid = threadIdx.x, lane = tid & 31, wid = tid >> 5;
    const int q0 = blockIdx.x * 128;
    const int h = blockIdx.y, b = blockIdx.z;
    const size_t hb = (size_t)(b * HH + h) * SS * DD;
    const uint32_t smb = smem_u32(sm);

    // ---- prologue: stage Q, mask adders ----
#pragma unroll
    for (int j = 0; j < 4; j++) {
        int idx = tid + 256 * j;
        int row = idx >> 3, ch = idx & 7;
        uint32_t so = sw128((uint32_t)(row * 128 + ch * 16));
        *(uint4*)(sm + so) = *(const uint4*)(g_Qh + hb + (size_t)(q0 + row) * DD + ch * 8);
    }
#pragma unroll
    for (int j = 0; j < SS / 256; j++) {
        int i = tid + 256 * j;
        ((float*)(sm + AADDER))[i] = mask[b * SS + i] ? 0.f : MASKADD;
    }
    __syncthreads();
    uint32_t qh[4][4];
    {
        int r = wid * 16 + (lane & 15);
#pragma unroll
        for (int kk = 0; kk < 4; kk++) {
            int cB = kk * 32 + (lane >> 4) * 16;
            ldsm4(qh[kk], smb + sw128((uint32_t)(r * 128 + cB)));
        }
    }
    // per-64-key-block "fully unmasked" flags
    if (tid < 32) {
        const float* ad = (const float*)(sm + AADDER) + tid * 64;
        int ok = 1;
#pragma unroll 8
        for (int i = 0; i < 64; i++) ok &= (ad[i] == 0.0f);
        ((int*)(sm + AFLAGS))[tid] = ok;
    }
    __syncthreads();

    auto issue = [&](int p, int s) {       // loads 128 keys (pair p) into stage s
        const uint32_t sb = smb + s * ASTAGE;
        const int c0 = p * 128;
#pragma unroll
        for (int j = 0; j < 4; j++) {
            int idx = tid + 256 * j;
            int row = idx >> 3, ch = idx & 7;
            uint32_t so = sw128((uint32_t)(row * 128 + ch * 16));
            size_t g = hb + (size_t)(c0 + row) * DD + ch * 8;
            cpa16(sb + so,         g_Kh + g);
            cpa16(sb + 16384 + so, g_Vh + g);
        }
        CPA_COMMIT();
    };

    float ctx[8][4];
#pragma unroll
    for (int i = 0; i < 8; i++)
#pragma unroll
        for (int j = 0; j < 4; j++) ctx[i][j] = 0.f;
    float lacc[4] = {0.f, 0.f, 0.f, 0.f};

    issue(0, 0); issue(1, 1); issue(2, 2);

    uint32_t off4[4];          // shared row/col pattern for K and V ldsm
    {
        const int rk = lane & 15;
#pragma unroll
        for (int i = 0; i < 4; i++) {
            const int cB = i * 32 + (lane >> 4) * 16;
            off4[i] = sw128((uint32_t)(rk * 128 + cB));
        }
    }
    const int kcol = 2 * (lane & 3);
    const int* flags = (const int*)(sm + AFLAGS);

    for (int p = 0; p < NPAIR; p++) {
        const int s = p % 3;
        const uint32_t sb = smb + s * ASTAGE;
        if (p <= NPAIR - 3) CPA_WAIT2();
        else if (p == NPAIR - 2) CPA_WAIT1();
        else CPA_WAIT0();
        __syncthreads();

#pragma unroll
        for (int hf = 0; hf < 2; hf++) {
            const int c = 2 * p + hf;
            const uint32_t koff = hf * 8192;

            // ---- S = Q K^T ----
            float sacc[8][4];
#pragma unroll
            for (int i = 0; i < 8; i++)
#pragma unroll
                for (int j = 0; j < 4; j++) sacc[i][j] = 0.f;

#pragma unroll
            for (int kk = 0; kk < 4; kk++) {
                const uint32_t ka = sb + koff + off4[kk];
#pragma unroll
                for (int g = 0; g < 4; g++) {
                    uint32_t kh[4];
                    ldsm4(kh, ka + g * 2048);
                    mma16816(sacc[2 * g],     qh[kk], kh[0], kh[2]);
                    mma16816(sacc[2 * g + 1], qh[kk], kh[1], kh[3]);
                }
            }

            // ---- softmax numerator: skip mask adds when block unmasked ----
            uint32_t ph[4][4];
            if (flags[c]) {
#pragma unroll
                for (int kg = 0; kg < 4; kg++) {
                    const float* s0 = sacc[2 * kg];
                    const float* s1 = sacc[2 * kg + 1];
                    ph[kg][0] = packh(exp2p(s0[0]), exp2p(s0[1]));
                    ph[kg][1] = packh(exp2p(s0[2]), exp2p(s0[3]));
                    ph[kg][2] = packh(exp2p(s1[0]), exp2p(s1[1]));
                    ph[kg][3] = packh(exp2p(s1[2]), exp2p(s1[3]));
                }
            } else {
                const float* madd = (const float*)(sm + AADDER) + c * 64;
#pragma unroll
                for (int kg = 0; kg < 4; kg++) {
                    const float* s0 = sacc[2 * kg];
                    const float* s1 = sacc[2 * kg + 1];
                    float a0 = madd[kg * 16 + kcol];
                    float a1 = madd[kg * 16 + kcol + 1];
                    float a2 = madd[kg * 16 + 8 + kcol];
                    float a3 = madd[kg * 16 + 8 + kcol + 1];
                    ph[kg][0] = packh(exp2p(s0[0] + a0), exp2p(s0[1] + a1));
                    ph[kg][1] = packh(exp2p(s0[2] + a0), exp2p(s0[3] + a1));
                    ph[kg][2] = packh(exp2p(s1[0] + a2), exp2p(s1[1] + a3));
                    ph[kg][3] = packh(exp2p(s1[2] + a2), exp2p(s1[3] + a3));
                }
            }

            // ---- l += P @ ones ----
#pragma unroll
            for (int kg = 0; kg < 4; kg++)
                mma16816(lacc, ph[kg], ONESF16X2, ONESF16X2);

            // ---- ctx += P V ----
#pragma unroll
            for (int dg = 0; dg < 4; dg++) {
                const uint32_t va = sb + 16384 + koff + off4[dg];
#pragma unroll
                for (int kg = 0; kg < 4; kg++) {
                    uint32_t vh[4];
                    ldsm4t(vh, va + kg * 2048);
                    mma16816(ctx[2 * dg],     ph[kg], vh[0], vh[1]);
                    mma16816(ctx[2 * dg + 1], ph[kg], vh[2], vh[3]);
                }
            }
        }
        __syncthreads();
        if (p + 3 < NPAIR) issue(p + 3, (p + 3) % 3);
    }

    // ---- write out [b, s, h*64 + d]; l fully reduced in lacc ----
    const float inv0 = 1.0f / lacc[0], inv1 = 1.0f / lacc[2];
    const int r0 = q0 + wid * 16 + (lane >> 2);
    const int dbase = 2 * (lane & 3);
#pragma unroll
    for (int nj = 0; nj < 8; nj++) {
        int d = nj * 8 + dbase;
        float2 v0 = make_float2(ctx[nj][0] * inv0, ctx[nj][1] * inv0);
        float2 v1 = make_float2(ctx[nj][2] * inv1, ctx[nj][3] * inv1);
        *(float2*)&out[(size_t)(b * SS + r0) * HID + h * DD + d] = v0;
        *(float2*)&out[(size_t)(b * SS + r0 + 8) * HID + h * DD + d] = v1;
    }
}

// ===================== launch =====================
extern "C" void kernel_launch(void* const* d_in, const int* in_sizes, int n_in,
                              void* d_out, int out_size) {
    const float* x    = (const float*)d_in[0];
    const int*   mask = (const int*)d_in[1];
    const float* Wq   = (const float*)d_in[2];
    const float* bq   = (const float*)d_in[3];
    const float* Wk   = (const float*)d_in[4];
    const float* bk   = (const float*)d_in[5];
    const float* Wv   = (const float*)d_in[6];
    const float* bv   = (const float*)d_in[7];
    float* out = (float*)d_out;

    static int attr_done = 0;
    if (!attr_done) {
        cudaFuncSetAttribute(qkv_gemm_mma,
                             cudaFuncAttributeMaxDynamicSharedMemorySize, GSMEM);
        cudaFuncSetAttribute(attn_mma,
                             cudaFuncAttributeMaxDynamicSharedMemorySize, ASMEM);
        attr_done = 1;
    }

    conv_x<<<(NTOK * HID) / 256, 256>>>(x);
    dim3 wgrid(HID / 32, HID / 32, 3);
    conv_w<<<wgrid, dim3(32, 32)>>>(Wq, Wk, Wv);

    dim3 ggrid(HID / 64, NTOK / 128, 3);
    qkv_gemm_mma<<<ggrid, 256, GSMEM>>>(bq, bk, bv);

    dim3 agrid(SS / 128, HH, BB);
    attn_mma<<<agrid, 256, ASMEM>>>(mask, out);
}

// round 14
// speedup vs baseline: 3.0056x; 1.1343x over previous
#include <cuda_runtime.h>
#include <cuda_fp16.h>
#include <math.h>
#include <stdint.h>

#define BB 2
#define SS 2048
#define HH 16
#define DD 64
#define HID 1024
#define NTOK (BB * SS)
#define LOG2E 1.4426950408889634f
#define QSCALE (0.125f * LOG2E)
#define MASKADD (-64.0f)     // log2-domain; exp2(-64) == 0 in fp16

// -------- scratch (allocation-free __device__ globals) --------
__device__ __half g_x[(size_t)NTOK * HID];               // x, fp16
__device__ __half g_Wth[(size_t)3 * HID * HID];          // W^T [n][k], fp16
__device__ __half g_Qh[(size_t)NTOK * HID];              // [b][h][s][d]
__device__ __half g_Kh[(size_t)NTOK * HID];
__device__ __half g_Vh[(size_t)NTOK * HID];

// ===================== helpers =====================
__device__ __forceinline__ uint32_t smem_u32(const void* p) {
    uint32_t a;
    asm("{ .reg .u64 t; cvta.to.shared.u64 t, %1; cvt.u32.u64 %0, t; }" : "=r"(a) : "l"(p));
    return a;
}
__device__ __forceinline__ uint32_t sw128(uint32_t o) { return o ^ ((o >> 3) & 0x70); }

__device__ __forceinline__ void ldsm4(uint32_t r[4], uint32_t addr) {
    asm volatile("ldmatrix.sync.aligned.m8n8.x4.shared.b16 {%0,%1,%2,%3}, [%4];"
                 : "=r"(r[0]), "=r"(r[1]), "=r"(r[2]), "=r"(r[3]) : "r"(addr));
}
__device__ __forceinline__ void ldsm4t(uint32_t r[4], uint32_t addr) {
    asm volatile("ldmatrix.sync.aligned.m8n8.x4.trans.shared.b16 {%0,%1,%2,%3}, [%4];"
                 : "=r"(r[0]), "=r"(r[1]), "=r"(r[2]), "=r"(r[3]) : "r"(addr));
}
// fp16 MMA, f32 accumulate
__device__ __forceinline__ void mma16816(float c[4], const uint32_t a[4],
                                         uint32_t b0, uint32_t b1) {
    asm volatile(
        "mma.sync.aligned.m16n8k16.row.col.f32.f16.f16.f32 "
        "{%0,%1,%2,%3}, {%4,%5,%6,%7}, {%8,%9}, {%0,%1,%2,%3};"
        : "+f"(c[0]), "+f"(c[1]), "+f"(c[2]), "+f"(c[3])
        : "r"(a[0]), "r"(a[1]), "r"(a[2]), "r"(a[3]), "r"(b0), "r"(b1));
}
// pack RN-fp16 pair: e0 -> low half, e1 -> high half
__device__ __forceinline__ uint32_t packh(float e0, float e1) {
    __half2 h = __floats2half2_rn(e0, e1);
    return *reinterpret_cast<uint32_t*>(&h);
}
// hardware exp2: one MUFU.EX2 (parallel pipe to tensor; ~2^-22 rel err)
__device__ __forceinline__ float ex2(float x) {
    float y;
    asm("ex2.approx.ftz.f32 %0, %1;" : "=f"(y) : "f"(x));
    return y;
}
__device__ __forceinline__ void cpa16(uint32_t s, const void* g) {
    asm volatile("cp.async.cg.shared.global [%0], [%1], 16;" :: "r"(s), "l"(g));
}
#define CPA_COMMIT() asm volatile("cp.async.commit_group;")
#define CPA_WAIT2()  asm volatile("cp.async.wait_group 2;")
#define CPA_WAIT1()  asm volatile("cp.async.wait_group 1;")
#define CPA_WAIT0()  asm volatile("cp.async.wait_group 0;")

#define ONESF16X2 0x3C003C00u     // half2(1.0, 1.0)

// ===================== prep kernels =====================
__global__ void conv_x(const float* __restrict__ x) {
    int i = blockIdx.x * 256 + threadIdx.x;
    g_x[i] = __float2half_rn(x[i]);
}

__global__ void conv_w(const float* __restrict__ Wq, const float* __restrict__ Wk,
                       const float* __restrict__ Wv) {
    __shared__ float t[32][33];
    int z = blockIdx.z;
    const float* W = (z == 0) ? Wq : (z == 1) ? Wk : Wv;
    int tx = threadIdx.x, ty = threadIdx.y;
    t[ty][tx] = W[(size_t)(blockIdx.y * 32 + ty) * HID + blockIdx.x * 32 + tx];
    __syncthreads();
    int n = blockIdx.x * 32 + ty;
    int k = blockIdx.y * 32 + tx;
    g_Wth[(size_t)z * HID * HID + (size_t)n * HID + k] = __float2half_rn(t[tx][ty]);
}

// ===================== QKV GEMM (single-term fp16: x*Wh) =====================
// BM=128, BN=64, BK=64. stage: A@0(16K) Bh@16K(8K) = 24K; 3 stages.
#define GSTAGE 24576
#define GSMEM  (3 * GSTAGE)      // 73728
#define NCHUNK 16

__global__ __launch_bounds__(256, 2)
void qkv_gemm_mma(const float* __restrict__ bq, const float* __restrict__ bk,
                  const float* __restrict__ bv) {
    extern __shared__ __align__(1024) char sm[];
    const int tid = threadIdx.x, lane = tid & 31, wid = tid >> 5;
    const int wm = wid & 3, wn = wid >> 2;
    const int z = blockIdx.z;
    const int m0 = blockIdx.y * 128;
    const int n0 = blockIdx.x * 64;

    const __half* Wh = g_Wth + (size_t)z * HID * HID;
    const float* bias = (z == 0) ? bq : (z == 1) ? bk : bv;
    const uint32_t smb = smem_u32(sm);

    auto issue = [&](int c, int s) {
        const uint32_t sb = smb + s * GSTAGE;
        const int k0 = c * 64;
#pragma unroll
        for (int j = 0; j < 4; j++) {               // A: 128 rows x 8 x 16B
            int idx = tid + 256 * j;
            int row = idx >> 3, ch = idx & 7;
            uint32_t so = sw128((uint32_t)(row * 128 + ch * 16));
            cpa16(sb + so, g_x + (size_t)(m0 + row) * HID + k0 + ch * 8);
        }
#pragma unroll
        for (int j = 0; j < 2; j++) {               // B: 64 rows x 8 x 16B
            int idx = tid + 256 * j;
            int row = idx >> 3, ch = idx & 7;
            uint32_t so = sw128((uint32_t)(row * 128 + ch * 16));
            cpa16(sb + 16384 + so, Wh + (size_t)(n0 + row) * HID + k0 + ch * 8);
        }
        CPA_COMMIT();
    };

    float acc[2][4][4];
#pragma unroll
    for (int i = 0; i < 2; i++)
#pragma unroll
        for (int j = 0; j < 4; j++)
#pragma unroll
            for (int v = 0; v < 4; v++) acc[i][j][v] = 0.f;

    issue(0, 0); issue(1, 1); issue(2, 2);

    uint32_t offA[4], offB[4];
    {
        const int rA = wm * 32 + (lane & 15);
        const int rB = wn * 32 + (lane & 15);
#pragma unroll
        for (int kk = 0; kk < 4; kk++) {
            const int cB = kk * 32 + (lane >> 4) * 16;
            offA[kk] = sw128((uint32_t)(rA * 128 + cB));
            offB[kk] = 16384 + sw128((uint32_t)(rB * 128 + cB));
        }
    }

    for (int c = 0; c < NCHUNK; c++) {
        const int s = c % 3;
        const uint32_t sb = smb + s * GSTAGE;
        if (c <= NCHUNK - 3) CPA_WAIT2();
        else if (c == NCHUNK - 2) CPA_WAIT1();
        else CPA_WAIT0();
        __syncthreads();

#pragma unroll
        for (int kk = 0; kk < 4; kk++) {
            const uint32_t aA = sb + offA[kk];
            const uint32_t aB = sb + offB[kk];
            uint32_t ah[2][4], bh[2][4];
            ldsm4(ah[0], aA);            ldsm4(ah[1], aA + 2048);
            ldsm4(bh[0], aB);            ldsm4(bh[1], aB + 2048);
#pragma unroll
            for (int g = 0; g < 2; g++) {
#pragma unroll
                for (int mi = 0; mi < 2; mi++) {
                    mma16816(acc[mi][2 * g],     ah[mi], bh[g][0], bh[g][2]);
                    mma16816(acc[mi][2 * g + 1], ah[mi], bh[g][1], bh[g][3]);
                }
            }
        }
        __syncthreads();
        if (c + 3 < NCHUNK) issue(c + 3, (c + 3) % 3);
    }

    __half* outh = (z == 0) ? g_Qh : (z == 1) ? g_Kh : g_Vh;
    const float sc = (z == 0) ? QSCALE : 1.0f;
#pragma unroll
    for (int mi = 0; mi < 2; mi++) {
        int r0 = m0 + wm * 32 + mi * 16 + (lane >> 2);
#pragma unroll
        for (int nj = 0; nj < 4; nj++) {
            int col = n0 + wn * 32 + nj * 8 + 2 * (lane & 3);
            float b0v = __ldg(&bias[col]), b1v = __ldg(&bias[col + 1]);
#pragma unroll
            for (int half_ = 0; half_ < 2; half_++) {
                int r = r0 + half_ * 8;
                float v0 = (acc[mi][nj][half_ * 2 + 0] + b0v) * sc;
                float v1 = (acc[mi][nj][half_ * 2 + 1] + b1v) * sc;
                size_t off = (((size_t)((r >> 11) * HH + (col >> 6)) * SS +
                               (r & (SS - 1))) * DD) + (col & (DD - 1));
                *(uint32_t*)(outh + off) = packh(v0, v1);
            }
        }
    }
}

// ===================== flash attention =====================
// 128-key stages (K 16K + V 16K = 32K), 3 stages; two 64-key halves per stage.
// adder floats @98304 (8K), block flags @106496 (32 ints).
#define ASTAGE 32768
#define AADDER (3 * ASTAGE)              // 98304
#define AFLAGS (AADDER + SS * 4)         // 106496
#define ASMEM  (AFLAGS + 128)            // 106624
#define NPAIR 16

__global__ __launch_bounds__(256, 2)
void attn_mma(const int* __restrict__ mask, float* __restrict__ out) {
    extern __shared__ __align__(1024) char sm[];
    const int tid = threadIdx.x, lane = tid & 31, wid = tid >> 5;
    const int q0 = blockIdx.x * 128;
    const int h = blockIdx.y, b = blockIdx.z;
    const size_t hb = (size_t)(b * HH + h) * SS * DD;
    const uint32_t smb = smem_u32(sm);

    // ---- prologue: stage Q, mask adders ----
#pragma unroll
    for (int j = 0; j < 4; j++) {
        int idx = tid + 256 * j;
        int row = idx >> 3, ch = idx & 7;
        uint32_t so = sw128((uint32_t)(row * 128 + ch * 16));
        *(uint4*)(sm + so) = *(const uint4*)(g_Qh + hb + (size_t)(q0 + row) * DD + ch * 8);
    }
#pragma unroll
    for (int j = 0; j < SS / 256; j++) {
        int i = tid + 256 * j;
        ((float*)(sm + AADDER))[i] = mask[b * SS + i] ? 0.f : MASKADD;
    }
    __syncthreads();
    uint32_t qh[4][4];
    {
        int r = wid * 16 + (lane & 15);
#pragma unroll
        for (int kk = 0; kk < 4; kk++) {
            int cB = kk * 32 + (lane >> 4) * 16;
            ldsm4(qh[kk], smb + sw128((uint32_t)(r * 128 + cB)));
        }
    }
    // per-64-key-block "fully unmasked" flags
    if (tid < 32) {
        const float* ad = (const float*)(sm + AADDER) + tid * 64;
        int ok = 1;
#pragma unroll 8
        for (int i = 0; i < 64; i++) ok &= (ad[i] == 0.0f);
        ((int*)(sm + AFLAGS))[tid] = ok;
    }
    __syncthreads();

    auto issue = [&](int p, int s) {       // loads 128 keys (pair p) into stage s
        const uint32_t sb = smb + s * ASTAGE;
        const int c0 = p * 128;
#pragma unroll
        for (int j = 0; j < 4; j++) {
            int idx = tid + 256 * j;
            int row = idx >> 3, ch = idx & 7;
            uint32_t so = sw128((uint32_t)(row * 128 + ch * 16));
            size_t g = hb + (size_t)(c0 + row) * DD + ch * 8;
            cpa16(sb + so,         g_Kh + g);
            cpa16(sb + 16384 + so, g_Vh + g);
        }
        CPA_COMMIT();
    };

    float ctx[8][4];
#pragma unroll
    for (int i = 0; i < 8; i++)
#pragma unroll
        for (int j = 0; j < 4; j++) ctx[i][j] = 0.f;
    float lacc[4] = {0.f, 0.f, 0.f, 0.f};

    issue(0, 0); issue(1, 1); issue(2, 2);

    uint32_t off4[4];          // shared row/col pattern for K and V ldsm
    {
        const int rk = lane & 15;
#pragma unroll
        for (int i = 0; i < 4; i++) {
            const int cB = i * 32 + (lane >> 4) * 16;
            off4[i] = sw128((uint32_t)(rk * 128 + cB));
        }
    }
    const int kcol = 2 * (lane & 3);
    const int* flags = (const int*)(sm + AFLAGS);

    for (int p = 0; p < NPAIR; p++) {
        const int s = p % 3;
        const uint32_t sb = smb + s * ASTAGE;
        if (p <= NPAIR - 3) CPA_WAIT2();
        else if (p == NPAIR - 2) CPA_WAIT1();
        else CPA_WAIT0();
        __syncthreads();

#pragma unroll
        for (int hf = 0; hf < 2; hf++) {
            const int c = 2 * p + hf;
            const uint32_t koff = hf * 8192;

            // ---- S = Q K^T ----
            float sacc[8][4];
#pragma unroll
            for (int i = 0; i < 8; i++)
#pragma unroll
                for (int j = 0; j < 4; j++) sacc[i][j] = 0.f;

#pragma unroll
            for (int kk = 0; kk < 4; kk++) {
                const uint32_t ka = sb + koff + off4[kk];
#pragma unroll
                for (int g = 0; g < 4; g++) {
                    uint32_t kh[4];
                    ldsm4(kh, ka + g * 2048);
                    mma16816(sacc[2 * g],     qh[kk], kh[0], kh[2]);
                    mma16816(sacc[2 * g + 1], qh[kk], kh[1], kh[3]);
                }
            }

            // ---- softmax numerator via MUFU.EX2; skip mask adds when unmasked ----
            uint32_t ph[4][4];
            if (flags[c]) {
#pragma unroll
                for (int kg = 0; kg < 4; kg++) {
                    const float* s0 = sacc[2 * kg];
                    const float* s1 = sacc[2 * kg + 1];
                    ph[kg][0] = packh(ex2(s0[0]), ex2(s0[1]));
                    ph[kg][1] = packh(ex2(s0[2]), ex2(s0[3]));
                    ph[kg][2] = packh(ex2(s1[0]), ex2(s1[1]));
                    ph[kg][3] = packh(ex2(s1[2]), ex2(s1[3]));
                }
            } else {
                const float* madd = (const float*)(sm + AADDER) + c * 64;
#pragma unroll
                for (int kg = 0; kg < 4; kg++) {
                    const float* s0 = sacc[2 * kg];
                    const float* s1 = sacc[2 * kg + 1];
                    float a0 = madd[kg * 16 + kcol];
                    float a1 = madd[kg * 16 + kcol + 1];
                    float a2 = madd[kg * 16 + 8 + kcol];
                    float a3 = madd[kg * 16 + 8 + kcol + 1];
                    ph[kg][0] = packh(ex2(s0[0] + a0), ex2(s0[1] + a1));
                    ph[kg][1] = packh(ex2(s0[2] + a0), ex2(s0[3] + a1));
                    ph[kg][2] = packh(ex2(s1[0] + a2), ex2(s1[1] + a3));
                    ph[kg][3] = packh(ex2(s1[2] + a2), ex2(s1[3] + a3));
                }
            }

            // ---- l += P @ ones ----
#pragma unroll
            for (int kg = 0; kg < 4; kg++)
                mma16816(lacc, ph[kg], ONESF16X2, ONESF16X2);

            // ---- ctx += P V ----
#pragma unroll
            for (int dg = 0; dg < 4; dg++) {
                const uint32_t va = sb + 16384 + koff + off4[dg];
#pragma unroll
                for (int kg = 0; kg < 4; kg++) {
                    uint32_t vh[4];
                    ldsm4t(vh, va + kg * 2048);
                    mma16816(ctx[2 * dg],     ph[kg], vh[0], vh[1]);
                    mma16816(ctx[2 * dg + 1], ph[kg], vh[2], vh[3]);
                }
            }
        }
        __syncthreads();
        if (p + 3 < NPAIR) issue(p + 3, (p + 3) % 3);
    }

    // ---- write out [b, s, h*64 + d]; l fully reduced in lacc ----
    const float inv0 = 1.0f / lacc[0], inv1 = 1.0f / lacc[2];
    const int r0 = q0 + wid * 16 + (lane >> 2);
    const int dbase = 2 * (lane & 3);
#pragma unroll
    for (int nj = 0; nj < 8; nj++) {
        int d = nj * 8 + dbase;
        float2 v0 = make_float2(ctx[nj][0] * inv0, ctx[nj][1] * inv0);
        float2 v1 = make_float2(ctx[nj][2] * inv1, ctx[nj][3] * inv1);
        *(float2*)&out[(size_t)(b * SS + r0) * HID + h * DD + d] = v0;
        *(float2*)&out[(size_t)(b * SS + r0 + 8) * HID + h * DD + d] = v1;
    }
}

// ===================== launch =====================
extern "C" void kernel_launch(void* const* d_in, const int* in_sizes, int n_in,
                              void* d_out, int out_size) {
    const float* x    = (const float*)d_in[0];
    const int*   mask = (const int*)d_in[1];
    const float* Wq   = (const float*)d_in[2];
    const float* bq   = (const float*)d_in[3];
    const float* Wk   = (const float*)d_in[4];
    const float* bk   = (const float*)d_in[5];
    const float* Wv   = (const float*)d_in[6];
    const float* bv   = (const float*)d_in[7];
    float* out = (float*)d_out;

    static int attr_done = 0;
    if (!attr_done) {
        cudaFuncSetAttribute(qkv_gemm_mma,
                             cudaFuncAttributeMaxDynamicSharedMemorySize, GSMEM);
        cudaFuncSetAttribute(attn_mma,
                             cudaFuncAttributeMaxDynamicSharedMemorySize, ASMEM);
        attr_done = 1;
    }

    conv_x<<<(NTOK * HID) / 256, 256>>>(x);
    dim3 wgrid(HID / 32, HID / 32, 3);
    conv_w<<<wgrid, dim3(32, 32)>>>(Wq, Wk, Wv);

    dim3 ggrid(HID / 64, NTOK / 128, 3);
    qkv_gemm_mma<<<ggrid, 256, GSMEM>>>(bq, bk, bv);

    dim3 agrid(SS / 128, HH, BB);
    attn_mma<<<agrid, 256, ASMEM>>>(mask, out);
}

// round 15
// speedup vs baseline: 3.0220x; 1.0055x over previous
#include <cuda_runtime.h>
#include <cuda_fp16.h>
#include <math.h>
#include <stdint.h>

#define BB 2
#define SS 2048
#define HH 16
#define DD 64
#define HID 1024
#define NTOK (BB * SS)
#define LOG2E 1.4426950408889634f
#define QSCALE (0.125f * LOG2E)
#define MASKADD (-64.0f)     // log2-domain; exp2(-64) == 0 in fp16

// -------- scratch (allocation-free __device__ globals) --------
__device__ __half g_x[(size_t)NTOK * HID];               // x, fp16
__device__ __half g_Wth[(size_t)3 * HID * HID];          // W^T [n][k], fp16
__device__ __half g_Qh[(size_t)NTOK * HID];              // [b][h][s][d]
__device__ __half g_Kh[(size_t)NTOK * HID];
__device__ __half g_Vh[(size_t)NTOK * HID];

// ===================== helpers =====================
__device__ __forceinline__ uint32_t smem_u32(const void* p) {
    uint32_t a;
    asm("{ .reg .u64 t; cvta.to.shared.u64 t, %1; cvt.u32.u64 %0, t; }" : "=r"(a) : "l"(p));
    return a;
}
__device__ __forceinline__ uint32_t sw128(uint32_t o) { return o ^ ((o >> 3) & 0x70); }

__device__ __forceinline__ void ldsm4(uint32_t r[4], uint32_t addr) {
    asm volatile("ldmatrix.sync.aligned.m8n8.x4.shared.b16 {%0,%1,%2,%3}, [%4];"
                 : "=r"(r[0]), "=r"(r[1]), "=r"(r[2]), "=r"(r[3]) : "r"(addr));
}
__device__ __forceinline__ void ldsm4t(uint32_t r[4], uint32_t addr) {
    asm volatile("ldmatrix.sync.aligned.m8n8.x4.trans.shared.b16 {%0,%1,%2,%3}, [%4];"
                 : "=r"(r[0]), "=r"(r[1]), "=r"(r[2]), "=r"(r[3]) : "r"(addr));
}
// fp16 MMA, f32 accumulate
__device__ __forceinline__ void mma16816(float c[4], const uint32_t a[4],
                                         uint32_t b0, uint32_t b1) {
    asm volatile(
        "mma.sync.aligned.m16n8k16.row.col.f32.f16.f16.f32 "
        "{%0,%1,%2,%3}, {%4,%5,%6,%7}, {%8,%9}, {%0,%1,%2,%3};"
        : "+f"(c[0]), "+f"(c[1]), "+f"(c[2]), "+f"(c[3])
        : "r"(a[0]), "r"(a[1]), "r"(a[2]), "r"(a[3]), "r"(b0), "r"(b1));
}
// pack RN-fp16 pair: e0 -> low half, e1 -> high half
__device__ __forceinline__ uint32_t packh(float e0, float e1) {
    __half2 h = __floats2half2_rn(e0, e1);
    return *reinterpret_cast<uint32_t*>(&h);
}
// hardware exp2: one MUFU.EX2 (parallel pipe to tensor)
__device__ __forceinline__ float ex2(float x) {
    float y;
    asm("ex2.approx.ftz.f32 %0, %1;" : "=f"(y) : "f"(x));
    return y;
}
__device__ __forceinline__ void cpa16(uint32_t s, const void* g) {
    asm volatile("cp.async.cg.shared.global [%0], [%1], 16;" :: "r"(s), "l"(g));
}
#define CPA_COMMIT() asm volatile("cp.async.commit_group;")
#define CPA_WAIT2()  asm volatile("cp.async.wait_group 2;")
#define CPA_WAIT1()  asm volatile("cp.async.wait_group 1;")
#define CPA_WAIT0()  asm volatile("cp.async.wait_group 0;")

#define ONESF16X2 0x3C003C00u     // half2(1.0, 1.0)

// ===================== fused prep: W transpose+convert (z<3), x convert (z==3) =====
__global__ void conv_all(const float* __restrict__ x,
                         const float* __restrict__ Wq, const float* __restrict__ Wk,
                         const float* __restrict__ Wv) {
    int z = blockIdx.z;
    int tx = threadIdx.x, ty = threadIdx.y;
    if (z < 3) {
        __shared__ float t[32][33];
        const float* W = (z == 0) ? Wq : (z == 1) ? Wk : Wv;
        t[ty][tx] = W[(size_t)(blockIdx.y * 32 + ty) * HID + blockIdx.x * 32 + tx];
        __syncthreads();
        int n = blockIdx.x * 32 + ty;
        int k = blockIdx.y * 32 + tx;
        g_Wth[(size_t)z * HID * HID + (size_t)n * HID + k] = __float2half_rn(t[tx][ty]);
    } else {
        // x convert: 1024 blocks x 1024 threads x 4 elems = 4.19M
        int bid = blockIdx.y * 32 + blockIdx.x;
        size_t i = ((size_t)bid * 1024 + ty * 32 + tx) * 4;
        float4 v = *(const float4*)(x + i);
        uint32_t p0 = packh(v.x, v.y), p1 = packh(v.z, v.w);
        *(uint2*)(g_x + i) = make_uint2(p0, p1);
    }
}

// ===================== QKV GEMM: BM128 x BN128 x BK64, warp tile 32x64 =============
// stage: A@0(16K) B@16K(16K) = 32K; 3 stages = 96K.
#define GSTAGE 32768
#define GSMEM  (3 * GSTAGE)      // 98304
#define NCHUNK 16

__global__ __launch_bounds__(256, 2)
void qkv_gemm_mma(const float* __restrict__ bq, const float* __restrict__ bk,
                  const float* __restrict__ bv) {
    extern __shared__ __align__(1024) char sm[];
    const int tid = threadIdx.x, lane = tid & 31, wid = tid >> 5;
    const int wm = wid >> 1, wn = wid & 1;     // 4m x 2n warp grid, 32x64 tiles
    const int z = blockIdx.z;
    const int m0 = blockIdx.y * 128;
    const int n0 = blockIdx.x * 128;

    const __half* Wh = g_Wth + (size_t)z * HID * HID;
    const float* bias = (z == 0) ? bq : (z == 1) ? bk : bv;
    const uint32_t smb = smem_u32(sm);

    auto issue = [&](int c, int s) {
        const uint32_t sb = smb + s * GSTAGE;
        const int k0 = c * 64;
#pragma unroll
        for (int j = 0; j < 4; j++) {               // A: 128 rows x 8 x 16B
            int idx = tid + 256 * j;
            int row = idx >> 3, ch = idx & 7;
            uint32_t so = sw128((uint32_t)(row * 128 + ch * 16));
            cpa16(sb + so, g_x + (size_t)(m0 + row) * HID + k0 + ch * 8);
        }
#pragma unroll
        for (int j = 0; j < 4; j++) {               // B: 128 n-rows x 8 x 16B
            int idx = tid + 256 * j;
            int row = idx >> 3, ch = idx & 7;
            uint32_t so = sw128((uint32_t)(row * 128 + ch * 16));
            cpa16(sb + 16384 + so, Wh + (size_t)(n0 + row) * HID + k0 + ch * 8);
        }
        CPA_COMMIT();
    };

    float acc[2][8][4];
#pragma unroll
    for (int i = 0; i < 2; i++)
#pragma unroll
        for (int j = 0; j < 8; j++)
#pragma unroll
            for (int v = 0; v < 4; v++) acc[i][j][v] = 0.f;

    issue(0, 0); issue(1, 1); issue(2, 2);

    uint32_t offA[4], offB[4];
    {
        const int rA = wm * 32 + (lane & 15);
        const int rB = wn * 64 + (lane & 15);
#pragma unroll
        for (int kk = 0; kk < 4; kk++) {
            const int cB = kk * 32 + (lane >> 4) * 16;
            offA[kk] = sw128((uint32_t)(rA * 128 + cB));
            offB[kk] = 16384 + sw128((uint32_t)(rB * 128 + cB));
        }
    }

    for (int c = 0; c < NCHUNK; c++) {
        const int s = c % 3;
        const uint32_t sb = smb + s * GSTAGE;
        if (c <= NCHUNK - 3) CPA_WAIT2();
        else if (c == NCHUNK - 2) CPA_WAIT1();
        else CPA_WAIT0();
        __syncthreads();

#pragma unroll
        for (int kk = 0; kk < 4; kk++) {
            const uint32_t aA = sb + offA[kk];
            const uint32_t aB = sb + offB[kk];
            uint32_t ah[2][4], bh[4][4];
            ldsm4(ah[0], aA);           ldsm4(ah[1], aA + 2048);
            ldsm4(bh[0], aB);           ldsm4(bh[1], aB + 2048);
            ldsm4(bh[2], aB + 4096);    ldsm4(bh[3], aB + 6144);
#pragma unroll
            for (int g = 0; g < 4; g++) {
#pragma unroll
                for (int mi = 0; mi < 2; mi++) {
                    mma16816(acc[mi][2 * g],     ah[mi], bh[g][0], bh[g][2]);
                    mma16816(acc[mi][2 * g + 1], ah[mi], bh[g][1], bh[g][3]);
                }
            }
        }
        __syncthreads();
        if (c + 3 < NCHUNK) issue(c + 3, (c + 3) % 3);
    }

    __half* outh = (z == 0) ? g_Qh : (z == 1) ? g_Kh : g_Vh;
    const float sc = (z == 0) ? QSCALE : 1.0f;
#pragma unroll
    for (int mi = 0; mi < 2; mi++) {
        int r0 = m0 + wm * 32 + mi * 16 + (lane >> 2);
#pragma unroll
        for (int nj = 0; nj < 8; nj++) {
            int col = n0 + wn * 64 + nj * 8 + 2 * (lane & 3);
            float b0v = __ldg(&bias[col]), b1v = __ldg(&bias[col + 1]);
#pragma unroll
            for (int half_ = 0; half_ < 2; half_++) {
                int r = r0 + half_ * 8;
                float v0 = (acc[mi][nj][half_ * 2 + 0] + b0v) * sc;
                float v1 = (acc[mi][nj][half_ * 2 + 1] + b1v) * sc;
                size_t off = (((size_t)((r >> 11) * HH + (col >> 6)) * SS +
                               (r & (SS - 1))) * DD) + (col & (DD - 1));
                *(uint32_t*)(outh + off) = packh(v0, v1);
            }
        }
    }
}

// ===================== flash attention (unchanged from R14) =====================
#define ASTAGE 32768
#define AADDER (3 * ASTAGE)              // 98304
#define AFLAGS (AADDER + SS * 4)         // 106496
#define ASMEM  (AFLAGS + 128)            // 106624
#define NPAIR 16

__global__ __launch_bounds__(256, 2)
void attn_mma(const int* __restrict__ mask, float* __restrict__ out) {
    extern __shared__ __align__(1024) char sm[];
    const int tid = threadIdx.x, lane = tid & 31, wid = tid >> 5;
    const int q0 = blockIdx.x * 128;
    const int h = blockIdx.y, b = blockIdx.z;
    const size_t hb = (size_t)(b * HH + h) * SS * DD;
    const uint32_t smb = smem_u32(sm);

    // ---- prologue: stage Q, mask adders ----
#pragma unroll
    for (int j = 0; j < 4; j++) {
        int idx = tid + 256 * j;
        int row = idx >> 3, ch = idx & 7;
        uint32_t so = sw128((uint32_t)(row * 128 + ch * 16));
        *(uint4*)(sm + so) = *(const uint4*)(g_Qh + hb + (size_t)(q0 + row) * DD + ch * 8);
    }
#pragma unroll
    for (int j = 0; j < SS / 256; j++) {
        int i = tid + 256 * j;
        ((float*)(sm + AADDER))[i] = mask[b * SS + i] ? 0.f : MASKADD;
    }
    __syncthreads();
    uint32_t qh[4][4];
    {
        int r = wid * 16 + (lane & 15);
#pragma unroll
        for (int kk = 0; kk < 4; kk++) {
            int cB = kk * 32 + (lane >> 4) * 16;
            ldsm4(qh[kk], smb + sw128((uint32_t)(r * 128 + cB)));
        }
    }
    // per-64-key-block "fully unmasked" flags
    if (tid < 32) {
        const float* ad = (const float*)(sm + AADDER) + tid * 64;
        int ok = 1;
#pragma unroll 8
        for (int i = 0; i < 64; i++) ok &= (ad[i] == 0.0f);
        ((int*)(sm + AFLAGS))[tid] = ok;
    }
    __syncthreads();

    auto issue = [&](int p, int s) {       // loads 128 keys (pair p) into stage s
        const uint32_t sb = smb + s * ASTAGE;
        const int c0 = p * 128;
#pragma unroll
        for (int j = 0; j < 4; j++) {
            int idx = tid + 256 * j;
            int row = idx >> 3, ch = idx & 7;
            uint32_t so = sw128((uint32_t)(row * 128 + ch * 16));
            size_t g = hb + (size_t)(c0 + row) * DD + ch * 8;
            cpa16(sb + so,         g_Kh + g);
            cpa16(sb + 16384 + so, g_Vh + g);
        }
        CPA_COMMIT();
    };

    float ctx[8][4];
#pragma unroll
    for (int i = 0; i < 8; i++)
#pragma unroll
        for (int j = 0; j < 4; j++) ctx[i][j] = 0.f;
    float lacc[4] = {0.f, 0.f, 0.f, 0.f};

    issue(0, 0); issue(1, 1); issue(2, 2);

    uint32_t off4[4];
    {
        const int rk = lane & 15;
#pragma unroll
        for (int i = 0; i < 4; i++) {
            const int cB = i * 32 + (lane >> 4) * 16;
            off4[i] = sw128((uint32_t)(rk * 128 + cB));
        }
    }
    const int kcol = 2 * (lane & 3);
    const int* flags = (const int*)(sm + AFLAGS);

    for (int p = 0; p < NPAIR; p++) {
        const int s = p % 3;
        const uint32_t sb = smb + s * ASTAGE;
        if (p <= NPAIR - 3) CPA_WAIT2();
        else if (p == NPAIR - 2) CPA_WAIT1();
        else CPA_WAIT0();
        __syncthreads();

#pragma unroll
        for (int hf = 0; hf < 2; hf++) {
            const int c = 2 * p + hf;
            const uint32_t koff = hf * 8192;

            float sacc[8][4];
#pragma unroll
            for (int i = 0; i < 8; i++)
#pragma unroll
                for (int j = 0; j < 4; j++) sacc[i][j] = 0.f;

#pragma unroll
            for (int kk = 0; kk < 4; kk++) {
                const uint32_t ka = sb + koff + off4[kk];
#pragma unroll
                for (int g = 0; g < 4; g++) {
                    uint32_t kh[4];
                    ldsm4(kh, ka + g * 2048);
                    mma16816(sacc[2 * g],     qh[kk], kh[0], kh[2]);
                    mma16816(sacc[2 * g + 1], qh[kk], kh[1], kh[3]);
                }
            }

            uint32_t ph[4][4];
            if (flags[c]) {
#pragma unroll
                for (int kg = 0; kg < 4; kg++) {
                    const float* s0 = sacc[2 * kg];
                    const float* s1 = sacc[2 * kg + 1];
                    ph[kg][0] = packh(ex2(s0[0]), ex2(s0[1]));
                    ph[kg][1] = packh(ex2(s0[2]), ex2(s0[3]));
                    ph[kg][2] = packh(ex2(s1[0]), ex2(s1[1]));
                    ph[kg][3] = packh(ex2(s1[2]), ex2(s1[3]));
                }
            } else {
                const float* madd = (const float*)(sm + AADDER) + c * 64;
#pragma unroll
                for (int kg = 0; kg < 4; kg++) {
                    const float* s0 = sacc[2 * kg];
                    const float* s1 = sacc[2 * kg + 1];
                    float a0 = madd[kg * 16 + kcol];
                    float a1 = madd[kg * 16 + kcol + 1];
                    float a2 = madd[kg * 16 + 8 + kcol];
                    float a3 = madd[kg * 16 + 8 + kcol + 1];
                    ph[kg][0] = packh(ex2(s0[0] + a0), ex2(s0[1] + a1));
                    ph[kg][1] = packh(ex2(s0[2] + a0), ex2(s0[3] + a1));
                    ph[kg][2] = packh(ex2(s1[0] + a2), ex2(s1[1] + a3));
                    ph[kg][3] = packh(ex2(s1[2] + a2), ex2(s1[3] + a3));
                }
            }

#pragma unroll
            for (int kg = 0; kg < 4; kg++)
                mma16816(lacc, ph[kg], ONESF16X2, ONESF16X2);

#pragma unroll
            for (int dg = 0; dg < 4; dg++) {
                const uint32_t va = sb + 16384 + koff + off4[dg];
#pragma unroll
                for (int kg = 0; kg < 4; kg++) {
                    uint32_t vh[4];
                    ldsm4t(vh, va + kg * 2048);
                    mma16816(ctx[2 * dg],     ph[kg], vh[0], vh[1]);
                    mma16816(ctx[2 * dg + 1], ph[kg], vh[2], vh[3]);
                }
            }
        }
        __syncthreads();
        if (p + 3 < NPAIR) issue(p + 3, (p + 3) % 3);
    }

    const float inv0 = 1.0f / lacc[0], inv1 = 1.0f / lacc[2];
    const int r0 = q0 + wid * 16 + (lane >> 2);
    const int dbase = 2 * (lane & 3);
#pragma unroll
    for (int nj = 0; nj < 8; nj++) {
        int d = nj * 8 + dbase;
        float2 v0 = make_float2(ctx[nj][0] * inv0, ctx[nj][1] * inv0);
        float2 v1 = make_float2(ctx[nj][2] * inv1, ctx[nj][3] * inv1);
        *(float2*)&out[(size_t)(b * SS + r0) * HID + h * DD + d] = v0;
        *(float2*)&out[(size_t)(b * SS + r0 + 8) * HID + h * DD + d] = v1;
    }
}

// ===================== launch =====================
extern "C" void kernel_launch(void* const* d_in, const int* in_sizes, int n_in,
                              void* d_out, int out_size) {
    const float* x    = (const float*)d_in[0];
    const int*   mask = (const int*)d_in[1];
    const float* Wq   = (const float*)d_in[2];
    const float* bq   = (const float*)d_in[3];
    const float* Wk   = (const float*)d_in[4];
    const float* bk   = (const float*)d_in[5];
    const float* Wv   = (const float*)d_in[6];
    const float* bv   = (const float*)d_in[7];
    float* out = (float*)d_out;

    static int attr_done = 0;
    if (!attr_done) {
        cudaFuncSetAttribute(qkv_gemm_mma,
                             cudaFuncAttributeMaxDynamicSharedMemorySize, GSMEM);
        cudaFuncSetAttribute(attn_mma,
                             cudaFuncAttributeMaxDynamicSharedMemorySize, ASMEM);
        attr_done = 1;
    }

    dim3 pgrid(32, 32, 4);
    conv_all<<<pgrid, dim3(32, 32)>>>(x, Wq, Wk, Wv);

    dim3 ggrid(HID / 128, NTOK / 128, 3);
    qkv_gemm_mma<<<ggrid, 256, GSMEM>>>(bq, bk, bv);

    dim3 agrid(SS / 128, HH, BB);
    attn_mma<<<agrid, 256, ASMEM>>>(mask, out);
}